// round 6
// baseline (speedup 1.0000x reference)
#include <cuda_runtime.h>
#include <cuda_bf16.h>
#include <math.h>

// Problem constants
#define NP 64
#define NR 8
#define NK 500
#define H_DIM 256
#define HEADS 8
#define HD 32
#define VD 8
#define B_DIM (NP*NR)          // 512
#define KCH 25                 // logits k-chunk (finer jobs)

#define GRID 440
#define TPB 256

#define NEG_INF (__int_as_float(0xff800000))

// ---------------- scratch ----------------
__device__ float g_Qg[B_DIM * H_DIM];
__device__ float g_xg[B_DIM * H_DIM];
__device__ float g_qm[B_DIM * H_DIM];
__device__ float g_L[B_DIM * NK];
__device__ unsigned g_flags;                 // mask dtype flags (idempotent)
__device__ unsigned g_cnt = 0;               // barrier arrivals (self-resetting)
__device__ unsigned g_gen = 0;               // barrier generation (monotonic)
__device__ unsigned g_q[6] = {0,0,0,0,0,0};  // per-stage job counters

// ---------------- global barrier, resets a queue counter ----------------
__device__ __forceinline__ void gsync(unsigned* reset_ctr) {
    __syncthreads();
    if (threadIdx.x == 0) {
        volatile unsigned* vgen = &g_gen;
        __threadfence();
        unsigned my = *vgen;
        unsigned v = atomicAdd(&g_cnt, 1u);
        if (v == (unsigned)(GRID - 1)) {
            g_cnt = 0u;
            if (reset_ctr) *reset_ctr = 0u;   // restore for next replay
            __threadfence();
            atomicAdd(&g_gen, 1u);            // release
        } else {
            while (*vgen == my) __nanosleep(32);
        }
        __threadfence();
    }
    __syncthreads();
}

// ---------------- helpers ----------------
__device__ __forceinline__ float tanh_fast(float x) {
    x = fminf(fmaxf(x, -15.f), 15.f);
    float e = __expf(2.f * x);
    return __fdividef(e - 1.f, e + 1.f);
}
__device__ __forceinline__ float tanh_approx(float x) {
    float y;
    asm("tanh.approx.f32 %0, %1;" : "=f"(y) : "f"(x));
    return y;
}
__device__ __forceinline__ float sigmoid_f(float x) {
    return 1.f / (1.f + __expf(-x));
}
__device__ __forceinline__ int load_maskmode() {
    unsigned f = *(volatile unsigned*)&g_flags;
    return (f & 2u) ? 2 : ((f & 1u) ? 1 : 0);
}
__device__ __forceinline__ bool get_mask(const void* m, int idx, int mode) {
    if (mode == 2) return ((const unsigned char*)m)[idx] != 0;
    if (mode == 1) return ((const float*)m)[idx] != 0.0f;
    return ((const int*)m)[idx] != 0;
}

// ---------------- shared memory ----------------
union SmemU {
    struct { float As[16][33]; float Bs[64][33]; } lstm;                        // 10.5KB
    struct { float As[16][33]; float Bs[32][33]; } gem;                         // 6.3KB
    struct { float Qs[NR*HD]; float Ss[NK*NR]; float xp[8][NR][HD]; float sinv[NR]; } attn; // 25.2KB
    struct { float qs[NR*H_DIM]; float As[VD*H_DIM]; float B[H_DIM]; float vfs[VD][KCH]; } lg; // 17.8KB
};
__shared__ SmemU sm;
__shared__ int s_job;

__device__ __forceinline__ int pull(unsigned* ctr) {
    __syncthreads();                          // also fences smem reuse
    if (threadIdx.x == 0) s_job = (int)atomicAdd(ctr, 1u);
    __syncthreads();
    return s_job;
}

// =========================== stages ===========================

__device__ void stage_probe(const unsigned int* __restrict__ m) {
    unsigned local = 0;
    int i = blockIdx.x * TPB + threadIdx.x;
    if (i < 64000) {
        unsigned v = m[i];
        if (v == 0x3F800000u) local |= 1u;
        else if (v > 1u) local |= 2u;
    }
#pragma unroll
    for (int o = 16; o; o >>= 1) local |= __shfl_xor_sync(0xffffffffu, local, o);
    if ((threadIdx.x & 31) == 0 && local) atomicOr(&g_flags, local);
}

// LSTM GEMM + fused activation. 512 tiles: 16 m x 16 cols (x4 gates).
__device__ void stage_lstm(const float* __restrict__ query,
                           const float* __restrict__ state1,
                           const float* __restrict__ Wih,
                           const float* __restrict__ Whh,
                           const float* __restrict__ bih,
                           const float* __restrict__ bhh,
                           const float* __restrict__ state2,
                           float* __restrict__ out) {
    int tid = threadIdx.x;
    int r = tid >> 5, c = tid & 31;          // loader coords
    int ty = tid >> 4, tx = tid & 15;        // compute: m = ty, col = tx
    for (;;) {
        int tile = pull(&g_q[0]);
        if (tile >= 512) break;
        int m0 = (tile >> 4) * 16;
        int colbase = (tile & 15) * 16;
        float acc[4] = {};
        int nrow[8];
#pragma unroll
        for (int i = 0; i < 8; ++i) {
            int j = r + i * 8;               // 0..63: gate = j>>4, col = j&15
            nrow[i] = (j >> 4) * 256 + colbase + (j & 15);
        }
        float ra[2], rb[8];
#pragma unroll
        for (int i = 0; i < 2; ++i) ra[i] = query[(m0 + r + i * 8) * 256 + c];
#pragma unroll
        for (int i = 0; i < 8; ++i) rb[i] = Wih[nrow[i] * 256 + c];
        for (int kt = 0; kt < 16; ++kt) {
#pragma unroll
            for (int i = 0; i < 2; ++i) sm.lstm.As[r + i * 8][c] = ra[i];
#pragma unroll
            for (int i = 0; i < 8; ++i) sm.lstm.Bs[r + i * 8][c] = rb[i];
            __syncthreads();
            if (kt < 15) {
                int kg = (kt + 1) * 32;
                const float* Ap = (kg < 256) ? query : state1;
                const float* Bp = (kg < 256) ? Wih : Whh;
                int kof = kg & 255;
#pragma unroll
                for (int i = 0; i < 2; ++i) ra[i] = Ap[(m0 + r + i * 8) * 256 + kof + c];
#pragma unroll
                for (int i = 0; i < 8; ++i) rb[i] = Bp[nrow[i] * 256 + kof + c];
            }
#pragma unroll
            for (int kk = 0; kk < 32; ++kk) {
                float a = sm.lstm.As[ty][kk];
#pragma unroll
                for (int g = 0; g < 4; ++g)
                    acc[g] = fmaf(a, sm.lstm.Bs[g * 16 + tx][kk], acc[g]);
            }
            __syncthreads();
        }
        int col = colbase + tx;
        int m = m0 + ty;
        int idx = m * 256 + col;
        float gi = acc[0] + bih[col]       + bhh[col];
        float gf = acc[1] + bih[256 + col] + bhh[256 + col];
        float gg = acc[2] + bih[512 + col] + bhh[512 + col];
        float go = acc[3] + bih[768 + col] + bhh[768 + col];
        float cc = sigmoid_f(gf) * state2[idx] + sigmoid_f(gi) * tanh_fast(gg);
        float hh = sigmoid_f(go) * tanh_fast(cc);
        out[idx] = hh;
        out[B_DIM * H_DIM + idx] = cc;
    }
}

// Generic 512x256x256 GEMM, tile 16m x 32n, 256 tiles.
__device__ void stage_gem(const float* __restrict__ A,
                          const float* __restrict__ Bm,
                          float* __restrict__ C, bool isQ, unsigned* ctr) {
    int tid = threadIdx.x;
    int r = tid >> 5, c = tid & 31;
    int ty = tid >> 5, tx = tid & 31;
    for (;;) {
        int tile = pull(ctr);
        if (tile >= 256) break;
        int m0 = (tile >> 3) * 16;
        int n0 = (tile & 7) * 32;
        float acc[2] = {};
        const float* Bbase = isQ ? (Bm + (n0 >> 5) * (H_DIM * HD)) : (Bm + n0);
        int bstride = isQ ? HD : H_DIM;
        float ra[2], rb[4];
#pragma unroll
        for (int i = 0; i < 2; ++i) ra[i] = A[(m0 + r + i * 8) * 256 + c];
#pragma unroll
        for (int i = 0; i < 4; ++i) rb[i] = Bbase[(r + i * 8) * bstride + c];
        for (int kt = 0; kt < 8; ++kt) {
#pragma unroll
            for (int i = 0; i < 2; ++i) sm.gem.As[r + i * 8][c] = ra[i];
#pragma unroll
            for (int i = 0; i < 4; ++i) sm.gem.Bs[r + i * 8][c] = rb[i];
            __syncthreads();
            if (kt < 7) {
                int k0 = (kt + 1) * 32;
#pragma unroll
                for (int i = 0; i < 2; ++i) ra[i] = A[(m0 + r + i * 8) * 256 + k0 + c];
#pragma unroll
                for (int i = 0; i < 4; ++i) rb[i] = Bbase[(k0 + r + i * 8) * bstride + c];
            }
#pragma unroll
            for (int kk = 0; kk < 32; ++kk) {
                float b = sm.gem.Bs[kk][tx];
                acc[0] = fmaf(sm.gem.As[ty * 2][kk], b, acc[0]);
                acc[1] = fmaf(sm.gem.As[ty * 2 + 1][kk], b, acc[1]);
            }
            __syncthreads();
        }
        float scale = isQ ? 0.17677669529663687f : 1.0f;
        C[(m0 + ty * 2) * 256 + n0 + tx]     = acc[0] * scale;
        C[(m0 + ty * 2 + 1) * 256 + n0 + tx] = acc[1] * scale;
    }
}

__device__ void stage_attn(const float* __restrict__ Kt,
                           const float* __restrict__ Vt,
                           const void* __restrict__ mask) {
    int tid = threadIdx.x;
    int w = tid >> 5, l = tid & 31;
    int mode = load_maskmode();
    for (;;) {
        int job = pull(&g_q[2]);
        if (job >= NP * HEADS) break;
        int p = job & 63, a = job >> 6;
        sm.attn.Qs[tid] = g_Qg[(p * NR + w) * H_DIM + a * HD + l];
        __syncthreads();

        // S pass: thread-per-k
        const float* Kbase = Kt + ((size_t)(a * NP + p)) * NK * HD;
        for (int k = tid; k < NK; k += 256) {
            const float4* kr = (const float4*)(Kbase + k * HD);
            float acc[NR] = {};
#pragma unroll
            for (int d4 = 0; d4 < 8; ++d4) {
                float4 kv = kr[d4];
#pragma unroll
                for (int q = 0; q < NR; ++q) {
                    float4 qv = *(const float4*)(sm.attn.Qs + q * HD + d4 * 4);
                    acc[q] = fmaf(qv.x, kv.x,
                             fmaf(qv.y, kv.y,
                             fmaf(qv.z, kv.z,
                             fmaf(qv.w, kv.w, acc[q]))));
                }
            }
            *(float4*)&sm.attn.Ss[k * 8]     = make_float4(acc[0], acc[1], acc[2], acc[3]);
            *(float4*)&sm.attn.Ss[k * 8 + 4] = make_float4(acc[4], acc[5], acc[6], acc[7]);
        }
        __syncthreads();

        // softmax per q (warp w = q)
        {
            int q = w;
            int mbase = p * (NR * NK) + q * NK;
            float mx = NEG_INF;
            for (int k = l; k < NK; k += 32) {
                float v = sm.attn.Ss[k * 8 + q];
                if (get_mask(mask, mbase + k, mode)) { v = NEG_INF; sm.attn.Ss[k * 8 + q] = v; }
                mx = fmaxf(mx, v);
            }
#pragma unroll
            for (int o = 16; o; o >>= 1) mx = fmaxf(mx, __shfl_xor_sync(0xffffffffu, mx, o));
            float s = 0.f;
            for (int k = l; k < NK; k += 32) {
                float e = __expf(sm.attn.Ss[k * 8 + q] - mx);
                sm.attn.Ss[k * 8 + q] = e;
                s += e;
            }
#pragma unroll
            for (int o = 16; o; o >>= 1) s += __shfl_xor_sync(0xffffffffu, s, o);
            if (l == 0) sm.attn.sinv[q] = 1.f / s;
        }
        __syncthreads();

        // x = P @ V : warp owns a k-chunk for all q
        {
            int k0 = (NK * w) / 8, k1 = (NK * (w + 1)) / 8;
            float acc[NR] = {};
            const float* Vb = Vt + ((size_t)(a * NP + p)) * NK * HD + l;
#pragma unroll 4
            for (int k = k0; k < k1; ++k) {
                float v = Vb[k * HD];
                float4 p0 = *(const float4*)&sm.attn.Ss[k * 8];
                float4 p1 = *(const float4*)&sm.attn.Ss[k * 8 + 4];
                acc[0] = fmaf(p0.x, v, acc[0]);
                acc[1] = fmaf(p0.y, v, acc[1]);
                acc[2] = fmaf(p0.z, v, acc[2]);
                acc[3] = fmaf(p0.w, v, acc[3]);
                acc[4] = fmaf(p1.x, v, acc[4]);
                acc[5] = fmaf(p1.y, v, acc[5]);
                acc[6] = fmaf(p1.z, v, acc[6]);
                acc[7] = fmaf(p1.w, v, acc[7]);
            }
#pragma unroll
            for (int q = 0; q < NR; ++q) sm.attn.xp[w][q][l] = acc[q];
        }
        __syncthreads();
        {
            float s = 0.f;
#pragma unroll
            for (int u = 0; u < 8; ++u) s += sm.attn.xp[u][w][l];
            g_xg[(p * NR + w) * H_DIM + a * HD + l] = s * sm.attn.sinv[w];
        }
    }
}

__device__ void stage_logits(const float* __restrict__ X,
                             const float* __restrict__ varfeat,
                             const void* __restrict__ mask,
                             const float* __restrict__ nnA,
                             const float* __restrict__ nnB,
                             const float* __restrict__ nnW) {
    int tid = threadIdx.x, w = tid >> 5, l = tid & 31;
    int mode = load_maskmode();
    float Wv[8];
#pragma unroll
    for (int j = 0; j < 8; ++j) Wv[j] = nnW[l + 32 * j];
    const int NJOB = NP * (NK / KCH);            // 64*20 = 1280
    for (;;) {
        int job = pull(&g_q[4]);
        if (job >= NJOB) break;
        int p = job / 20;
        int kbase = (job % 20) * KCH;
        for (int e = tid; e < NR * H_DIM; e += 256) {
            sm.lg.qs[e] = g_qm[p * NR * H_DIM + e];
            sm.lg.As[e] = nnA[e];
        }
        sm.lg.B[tid] = nnB[tid];
        if (tid < VD * KCH) {
            int v = tid / KCH, kk = tid % KCH;
            sm.lg.vfs[v][kk] = varfeat[(p * VD + v) * NK + kbase + kk];
        }
        __syncthreads();

        for (int k = kbase + w; k < kbase + KCH; k += 8) {
            int kk = k - kbase;
            const float* Xr = X + ((size_t)p * NK + k) * H_DIM;
            float base[8];
#pragma unroll
            for (int j = 0; j < 8; ++j) base[j] = Xr[l + 32 * j] + sm.lg.B[l + 32 * j];
#pragma unroll
            for (int v = 0; v < VD; ++v) {
                float f = sm.lg.vfs[v][kk];
#pragma unroll
                for (int j = 0; j < 8; ++j)
                    base[j] = fmaf(f, sm.lg.As[v * H_DIM + l + 32 * j], base[j]);
            }
            int mb = p * (NR * NK) + k;
#pragma unroll
            for (int q = 0; q < NR; ++q) {
                float outv;
                if (get_mask(mask, mb + q * NK, mode)) {
                    outv = NEG_INF;
                } else {
                    float s = 0.f;
#pragma unroll
                    for (int j = 0; j < 8; ++j)
                        s = fmaf(tanh_approx(base[j] + sm.lg.qs[q * H_DIM + l + 32 * j]), Wv[j], s);
#pragma unroll
                    for (int o = 16; o; o >>= 1) s += __shfl_xor_sync(0xffffffffu, s, o);
                    outv = 10.f * tanh_fast(s);
                }
                if (l == 0) g_L[(p * NR + q) * NK + k] = outv;
            }
        }
    }
}

__device__ void stage_choose(float* __restrict__ out) {
    int w = threadIdx.x >> 5, l = threadIdx.x & 31;
    int r = blockIdx.x * 8 + w;
    if (r >= B_DIM) return;
    const float* Lr = g_L + r * NK;
    float best = NEG_INF;
    for (int k = l; k < NK; k += 32) best = fmaxf(best, Lr[k]);
#pragma unroll
    for (int o = 16; o; o >>= 1) best = fmaxf(best, __shfl_xor_sync(0xffffffffu, best, o));
    float s = 0.f;
    for (int k = l; k < NK; k += 32) {
        float v = Lr[k];
        if (v > NEG_INF) s += __expf(v - best);
    }
#pragma unroll
    for (int o = 16; o; o >>= 1) s += __shfl_xor_sync(0xffffffffu, s, o);
    if (l == 0) out[2 * B_DIM * H_DIM + r] = -logf(s);
}

// =========================== persistent kernel ===========================
__global__ __launch_bounds__(TPB, 3)
void decode_persistent(const float* __restrict__ X,
                       const float* __restrict__ Kt,
                       const float* __restrict__ Vt,
                       const float* __restrict__ query,
                       const float* __restrict__ state1,
                       const float* __restrict__ state2,
                       const float* __restrict__ varfeat,
                       const void*  __restrict__ mask,
                       const float* __restrict__ nnQ,
                       const float* __restrict__ nnO,
                       const float* __restrict__ nnA,
                       const float* __restrict__ nnB,
                       const float* __restrict__ nnW,
                       const float* __restrict__ Wih,
                       const float* __restrict__ Whh,
                       const float* __restrict__ bih,
                       const float* __restrict__ bhh,
                       float* __restrict__ out) {
    stage_probe((const unsigned int*)mask);
    stage_lstm(query, state1, Wih, Whh, bih, bhh, state2, out);
    gsync(&g_q[0]);                                 // h,c + flags visible
    stage_gem(out, nnQ, g_Qg, true, &g_q[1]);       // Q projection
    gsync(&g_q[1]);
    stage_attn(Kt, Vt, mask);                       // -> g_xg
    gsync(&g_q[2]);
    stage_gem(g_xg, nnO, g_qm, false, &g_q[3]);     // qm
    gsync(&g_q[3]);
    stage_logits(X, varfeat, mask, nnA, nnB, nnW);  // -> g_L
    gsync(&g_q[4]);
    stage_choose(out);
}

// ---------------- launch ----------------
extern "C" void kernel_launch(void* const* d_in, const int* in_sizes, int n_in,
                              void* d_out, int out_size) {
    const float* X       = (const float*)d_in[0];
    const float* Kt      = (const float*)d_in[1];
    const float* Vt      = (const float*)d_in[2];
    const float* query   = (const float*)d_in[3];
    const float* state1  = (const float*)d_in[4];
    const float* state2  = (const float*)d_in[5];
    const float* varfeat = (const float*)d_in[6];
    const void*  mask    = (const void*) d_in[7];
    const float* nnQ     = (const float*)d_in[8];
    const float* nnO     = (const float*)d_in[9];
    const float* nnA     = (const float*)d_in[10];
    const float* nnB     = (const float*)d_in[11];
    const float* nnW     = (const float*)d_in[12];
    const float* Wih     = (const float*)d_in[13];
    const float* Whh     = (const float*)d_in[14];
    const float* bih     = (const float*)d_in[15];
    const float* bhh     = (const float*)d_in[16];
    float* out = (float*)d_out;

    decode_persistent<<<GRID, TPB>>>(X, Kt, Vt, query, state1, state2, varfeat,
                                     mask, nnQ, nnO, nnA, nnB, nnW,
                                     Wih, Whh, bih, bhh, out);
}

// round 7
// speedup vs baseline: 1.3124x; 1.3124x over previous
#include <cuda_runtime.h>
#include <cuda_bf16.h>
#include <math.h>

// Problem constants
#define NP 64
#define NR 8
#define NK 500
#define H_DIM 256
#define HEADS 8
#define HD 32
#define VD 8
#define B_DIM (NP*NR)          // 512
#define KCH 25

#define GRID 264
#define TPB 256

#define NEG_INF (__int_as_float(0xff800000))

// ---------------- scratch ----------------
__device__ float g_Qg[B_DIM * H_DIM];
__device__ float g_xg[B_DIM * H_DIM];
__device__ float g_qm[B_DIM * H_DIM];
__device__ float g_L[B_DIM * NK];
__device__ unsigned g_flags;
__device__ unsigned g_cnt = 0;
__device__ unsigned g_gen = 0;

// ---------------- global software barrier (replay-safe) ----------------
__device__ __forceinline__ void gsync() {
    __syncthreads();
    if (threadIdx.x == 0) {
        volatile unsigned* vgen = &g_gen;
        __threadfence();
        unsigned my = *vgen;
        unsigned v = atomicAdd(&g_cnt, 1u);
        if (v == (unsigned)(GRID - 1)) {
            g_cnt = 0u;
            __threadfence();
            atomicAdd(&g_gen, 1u);
        } else {
            while (*vgen == my) __nanosleep(32);
        }
        __threadfence();
    }
    __syncthreads();
}

// ---------------- helpers ----------------
__device__ __forceinline__ float tanh_fast(float x) {
    x = fminf(fmaxf(x, -15.f), 15.f);
    float e = __expf(2.f * x);
    return __fdividef(e - 1.f, e + 1.f);
}
__device__ __forceinline__ float tanh_approx(float x) {
    float y;
    asm("tanh.approx.f32 %0, %1;" : "=f"(y) : "f"(x));
    return y;
}
__device__ __forceinline__ float sigmoid_f(float x) {
    return 1.f / (1.f + __expf(-x));
}
__device__ __forceinline__ int load_maskmode() {
    unsigned f = *(volatile unsigned*)&g_flags;
    return (f & 2u) ? 2 : ((f & 1u) ? 1 : 0);
}
__device__ __forceinline__ bool get_mask(const void* m, int idx, int mode) {
    if (mode == 2) return ((const unsigned char*)m)[idx] != 0;
    if (mode == 1) return ((const float*)m)[idx] != 0.0f;
    return ((const int*)m)[idx] != 0;
}
__device__ __forceinline__ float dot4(float4 a, float4 b, float acc) {
    return fmaf(a.x, b.x, fmaf(a.y, b.y, fmaf(a.z, b.z, fmaf(a.w, b.w, acc))));
}

// ---------------- shared memory ----------------
union SmemU {
    struct { float As[32][36]; float Bs[64][36]; } lstm;                        // 13.8KB
    struct { float As[16][36]; float BsT[32][36]; } gem;                        // 6.9KB
    struct { float Qs[NR*HD]; float Ss[NK*NR]; float xp[8][NR][HD]; float sinv[NR]; } attn; // 25.2KB
    struct { float qs[NR*H_DIM]; float As[VD*H_DIM]; float B[H_DIM]; float vfs[VD][KCH]; } lg; // 17.8KB
};
__shared__ SmemU sm;

// =========================== stages ===========================

__device__ void stage_probe(const unsigned int* __restrict__ m) {
    unsigned local = 0;
    for (int i = blockIdx.x * TPB + threadIdx.x; i < 64000; i += GRID * TPB) {
        unsigned v = m[i];
        if (v == 0x3F800000u) local |= 1u;
        else if (v > 1u) local |= 2u;
    }
#pragma unroll
    for (int o = 16; o; o >>= 1) local |= __shfl_xor_sync(0xffffffffu, local, o);
    if ((threadIdx.x & 31) == 0 && local) atomicOr(&g_flags, local);
}

// LSTM GEMM + fused activation. 256 tiles: 32 m x 16 cols (x4 gates).
__device__ void stage_lstm(const float* __restrict__ query,
                           const float* __restrict__ state1,
                           const float* __restrict__ Wih,
                           const float* __restrict__ Whh,
                           const float* __restrict__ bih,
                           const float* __restrict__ bhh,
                           const float* __restrict__ state2,
                           float* __restrict__ out) {
    int tile = blockIdx.x;
    if (tile >= 256) return;
    int m0 = (tile >> 4) * 32;
    int colbase = (tile & 15) * 16;
    int tid = threadIdx.x;
    int r = tid >> 5, c = tid & 31;          // loader coords
    int ty = tid >> 4, tx = tid & 15;        // compute: m pair = ty, col = tx
    float acc[2][4] = {};
    int nrow[8];
#pragma unroll
    for (int i = 0; i < 8; ++i) {
        int j = r + i * 8;                   // 0..63: gate = j>>4, col = j&15
        nrow[i] = (j >> 4) * 256 + colbase + (j & 15);
    }
    float ra[4], rb[8];
#pragma unroll
    for (int i = 0; i < 4; ++i) ra[i] = query[(m0 + r + i * 8) * 256 + c];
#pragma unroll
    for (int i = 0; i < 8; ++i) rb[i] = Wih[nrow[i] * 256 + c];
    for (int kt = 0; kt < 16; ++kt) {
#pragma unroll
        for (int i = 0; i < 4; ++i) sm.lstm.As[r + i * 8][c] = ra[i];
#pragma unroll
        for (int i = 0; i < 8; ++i) sm.lstm.Bs[r + i * 8][c] = rb[i];
        __syncthreads();
        if (kt < 15) {
            int kg = (kt + 1) * 32;
            const float* Ap = (kg < 256) ? query : state1;
            const float* Bp = (kg < 256) ? Wih : Whh;
            int kof = kg & 255;
#pragma unroll
            for (int i = 0; i < 4; ++i) ra[i] = Ap[(m0 + r + i * 8) * 256 + kof + c];
#pragma unroll
            for (int i = 0; i < 8; ++i) rb[i] = Bp[nrow[i] * 256 + kof + c];
        }
#pragma unroll
        for (int kc = 0; kc < 8; ++kc) {
            float4 a0 = *(const float4*)&sm.lstm.As[ty * 2][kc * 4];
            float4 a1 = *(const float4*)&sm.lstm.As[ty * 2 + 1][kc * 4];
#pragma unroll
            for (int g = 0; g < 4; ++g) {
                float4 b = *(const float4*)&sm.lstm.Bs[g * 16 + tx][kc * 4];
                acc[0][g] = dot4(a0, b, acc[0][g]);
                acc[1][g] = dot4(a1, b, acc[1][g]);
            }
        }
        __syncthreads();
    }
    int col = colbase + tx;
#pragma unroll
    for (int i = 0; i < 2; ++i) {
        int m = m0 + ty * 2 + i;
        int idx = m * 256 + col;
        float gi = acc[i][0] + bih[col]       + bhh[col];
        float gf = acc[i][1] + bih[256 + col] + bhh[256 + col];
        float gg = acc[i][2] + bih[512 + col] + bhh[512 + col];
        float go = acc[i][3] + bih[768 + col] + bhh[768 + col];
        float cc = sigmoid_f(gf) * state2[idx] + sigmoid_f(gi) * tanh_fast(gg);
        float hh = sigmoid_f(go) * tanh_fast(cc);
        out[idx] = hh;
        out[B_DIM * H_DIM + idx] = cc;
    }
}

// Generic 512x256x256 GEMM, tile 16m x 32n, 256 tiles. B staged transposed.
__device__ void stage_gem(const float* __restrict__ A,
                          const float* __restrict__ Bm,
                          float* __restrict__ C, bool isQ) {
    int tile = blockIdx.x;
    if (tile >= 256) return;
    int m0 = (tile >> 3) * 16;
    int n0 = (tile & 7) * 32;
    int tid = threadIdx.x;
    int r = tid >> 5, c = tid & 31;
    int ty = tid >> 5, tx = tid & 31;
    float acc[2] = {};
    const float* Bbase = isQ ? (Bm + (n0 >> 5) * (H_DIM * HD)) : (Bm + n0);
    int bstride = isQ ? HD : H_DIM;
    float ra[2], rb[4];
#pragma unroll
    for (int i = 0; i < 2; ++i) ra[i] = A[(m0 + r + i * 8) * 256 + c];
#pragma unroll
    for (int i = 0; i < 4; ++i) rb[i] = Bbase[(r + i * 8) * bstride + c];
    for (int kt = 0; kt < 8; ++kt) {
#pragma unroll
        for (int i = 0; i < 2; ++i) sm.gem.As[r + i * 8][c] = ra[i];
#pragma unroll
        for (int i = 0; i < 4; ++i) sm.gem.BsT[c][r + i * 8] = rb[i];   // transpose
        __syncthreads();
        if (kt < 7) {
            int k0 = (kt + 1) * 32;
#pragma unroll
            for (int i = 0; i < 2; ++i) ra[i] = A[(m0 + r + i * 8) * 256 + k0 + c];
#pragma unroll
            for (int i = 0; i < 4; ++i) rb[i] = Bbase[(k0 + r + i * 8) * bstride + c];
        }
#pragma unroll
        for (int kc = 0; kc < 8; ++kc) {
            float4 a0 = *(const float4*)&sm.gem.As[ty * 2][kc * 4];
            float4 a1 = *(const float4*)&sm.gem.As[ty * 2 + 1][kc * 4];
            float4 b  = *(const float4*)&sm.gem.BsT[tx][kc * 4];
            acc[0] = dot4(a0, b, acc[0]);
            acc[1] = dot4(a1, b, acc[1]);
        }
        __syncthreads();
    }
    float scale = isQ ? 0.17677669529663687f : 1.0f;
    C[(m0 + ty * 2) * 256 + n0 + tx]     = acc[0] * scale;
    C[(m0 + ty * 2 + 1) * 256 + n0 + tx] = acc[1] * scale;
}

__device__ void stage_attn(const float* __restrict__ Kt,
                           const float* __restrict__ Vt,
                           const void* __restrict__ mask) {
    int tid = threadIdx.x;
    int w = tid >> 5, l = tid & 31;
    int mode = load_maskmode();
    for (int job = blockIdx.x; job < NP * HEADS; job += GRID) {
        int p = job & 63, a = job >> 6;
        __syncthreads();
        sm.attn.Qs[tid] = g_Qg[(p * NR + w) * H_DIM + a * HD + l];
        __syncthreads();

        // S pass: thread-per-k
        const float* Kbase = Kt + ((size_t)(a * NP + p)) * NK * HD;
        for (int k = tid; k < NK; k += 256) {
            const float4* kr = (const float4*)(Kbase + k * HD);
            float acc[NR] = {};
#pragma unroll
            for (int d4 = 0; d4 < 8; ++d4) {
                float4 kv = kr[d4];
#pragma unroll
                for (int q = 0; q < NR; ++q) {
                    float4 qv = *(const float4*)(sm.attn.Qs + q * HD + d4 * 4);
                    acc[q] = dot4(qv, kv, acc[q]);
                }
            }
            *(float4*)&sm.attn.Ss[k * 8]     = make_float4(acc[0], acc[1], acc[2], acc[3]);
            *(float4*)&sm.attn.Ss[k * 8 + 4] = make_float4(acc[4], acc[5], acc[6], acc[7]);
        }
        __syncthreads();

        // softmax per q (warp w = q)
        {
            int q = w;
            int mbase = p * (NR * NK) + q * NK;
            float mx = NEG_INF;
            for (int k = l; k < NK; k += 32) {
                float v = sm.attn.Ss[k * 8 + q];
                if (get_mask(mask, mbase + k, mode)) { v = NEG_INF; sm.attn.Ss[k * 8 + q] = v; }
                mx = fmaxf(mx, v);
            }
#pragma unroll
            for (int o = 16; o; o >>= 1) mx = fmaxf(mx, __shfl_xor_sync(0xffffffffu, mx, o));
            float s = 0.f;
            for (int k = l; k < NK; k += 32) {
                float e = __expf(sm.attn.Ss[k * 8 + q] - mx);
                sm.attn.Ss[k * 8 + q] = e;
                s += e;
            }
#pragma unroll
            for (int o = 16; o; o >>= 1) s += __shfl_xor_sync(0xffffffffu, s, o);
            if (l == 0) sm.attn.sinv[q] = 1.f / s;
        }
        __syncthreads();

        // x = P @ V : warp owns a k-chunk for all q
        {
            int k0 = (NK * w) / 8, k1 = (NK * (w + 1)) / 8;
            float acc[NR] = {};
            const float* Vb = Vt + ((size_t)(a * NP + p)) * NK * HD + l;
#pragma unroll 4
            for (int k = k0; k < k1; ++k) {
                float v = Vb[k * HD];
                float4 p0 = *(const float4*)&sm.attn.Ss[k * 8];
                float4 p1 = *(const float4*)&sm.attn.Ss[k * 8 + 4];
                acc[0] = fmaf(p0.x, v, acc[0]);
                acc[1] = fmaf(p0.y, v, acc[1]);
                acc[2] = fmaf(p0.z, v, acc[2]);
                acc[3] = fmaf(p0.w, v, acc[3]);
                acc[4] = fmaf(p1.x, v, acc[4]);
                acc[5] = fmaf(p1.y, v, acc[5]);
                acc[6] = fmaf(p1.z, v, acc[6]);
                acc[7] = fmaf(p1.w, v, acc[7]);
            }
#pragma unroll
            for (int q = 0; q < NR; ++q) sm.attn.xp[w][q][l] = acc[q];
        }
        __syncthreads();
        {
            float s = 0.f;
#pragma unroll
            for (int u = 0; u < 8; ++u) s += sm.attn.xp[u][w][l];
            g_xg[(p * NR + w) * H_DIM + a * HD + l] = s * sm.attn.sinv[w];
        }
    }
}

// logits: lane l owns h = l*8 .. l*8+7 (contiguous, vectorized loads)
__device__ void stage_logits(const float* __restrict__ X,
                             const float* __restrict__ varfeat,
                             const void* __restrict__ mask,
                             const float* __restrict__ nnA,
                             const float* __restrict__ nnB,
                             const float* __restrict__ nnW) {
    int tid = threadIdx.x, w = tid >> 5, l = tid & 31;
    int mode = load_maskmode();
    float4 Wv0 = *(const float4*)(nnW + l * 8);
    float4 Wv1 = *(const float4*)(nnW + l * 8 + 4);
    const int NJOB = NP * (NK / KCH);            // 1280
    for (int job = blockIdx.x; job < NJOB; job += GRID) {
        int p = job / 20;
        int kbase = (job % 20) * KCH;
        __syncthreads();
        for (int e = tid; e < NR * H_DIM; e += 256) {
            sm.lg.qs[e] = g_qm[p * NR * H_DIM + e];
            sm.lg.As[e] = nnA[e];
        }
        sm.lg.B[tid] = nnB[tid];
        if (tid < VD * KCH) {
            int v = tid / KCH, kk = tid % KCH;
            sm.lg.vfs[v][kk] = varfeat[(p * VD + v) * NK + kbase + kk];
        }
        __syncthreads();

        float4 B0 = *(const float4*)&sm.lg.B[l * 8];
        float4 B1 = *(const float4*)&sm.lg.B[l * 8 + 4];

        for (int k = kbase + w; k < kbase + KCH; k += 8) {
            int kk = k - kbase;
            const float* Xr = X + ((size_t)p * NK + k) * H_DIM + l * 8;
            float4 x0 = *(const float4*)Xr;
            float4 x1 = *(const float4*)(Xr + 4);
            float base[8];
            base[0] = x0.x + B0.x; base[1] = x0.y + B0.y;
            base[2] = x0.z + B0.z; base[3] = x0.w + B0.w;
            base[4] = x1.x + B1.x; base[5] = x1.y + B1.y;
            base[6] = x1.z + B1.z; base[7] = x1.w + B1.w;
#pragma unroll
            for (int v = 0; v < VD; ++v) {
                float f = sm.lg.vfs[v][kk];
                float4 a0 = *(const float4*)&sm.lg.As[v * H_DIM + l * 8];
                float4 a1 = *(const float4*)&sm.lg.As[v * H_DIM + l * 8 + 4];
                base[0] = fmaf(f, a0.x, base[0]); base[1] = fmaf(f, a0.y, base[1]);
                base[2] = fmaf(f, a0.z, base[2]); base[3] = fmaf(f, a0.w, base[3]);
                base[4] = fmaf(f, a1.x, base[4]); base[5] = fmaf(f, a1.y, base[5]);
                base[6] = fmaf(f, a1.z, base[6]); base[7] = fmaf(f, a1.w, base[7]);
            }
            int mb = p * (NR * NK) + k;
#pragma unroll
            for (int q = 0; q < NR; ++q) {
                float outv;
                if (get_mask(mask, mb + q * NK, mode)) {
                    outv = NEG_INF;
                } else {
                    float4 q0 = *(const float4*)&sm.lg.qs[q * H_DIM + l * 8];
                    float4 q1 = *(const float4*)&sm.lg.qs[q * H_DIM + l * 8 + 4];
                    float s;
                    s = tanh_approx(base[0] + q0.x) * Wv0.x;
                    s = fmaf(tanh_approx(base[1] + q0.y), Wv0.y, s);
                    s = fmaf(tanh_approx(base[2] + q0.z), Wv0.z, s);
                    s = fmaf(tanh_approx(base[3] + q0.w), Wv0.w, s);
                    s = fmaf(tanh_approx(base[4] + q1.x), Wv1.x, s);
                    s = fmaf(tanh_approx(base[5] + q1.y), Wv1.y, s);
                    s = fmaf(tanh_approx(base[6] + q1.z), Wv1.z, s);
                    s = fmaf(tanh_approx(base[7] + q1.w), Wv1.w, s);
#pragma unroll
                    for (int o = 16; o; o >>= 1) s += __shfl_xor_sync(0xffffffffu, s, o);
                    outv = 10.f * tanh_fast(s);
                }
                if (l == 0) g_L[(p * NR + q) * NK + k] = outv;
            }
        }
    }
}

__device__ void stage_choose(float* __restrict__ out) {
    int w = threadIdx.x >> 5, l = threadIdx.x & 31;
    int r = blockIdx.x * 8 + w;
    if (r >= B_DIM) return;
    const float* Lr = g_L + r * NK;
    float best = NEG_INF;
    for (int k = l; k < NK; k += 32) best = fmaxf(best, Lr[k]);
#pragma unroll
    for (int o = 16; o; o >>= 1) best = fmaxf(best, __shfl_xor_sync(0xffffffffu, best, o));
    float s = 0.f;
    for (int k = l; k < NK; k += 32) {
        float v = Lr[k];
        if (v > NEG_INF) s += __expf(v - best);
    }
#pragma unroll
    for (int o = 16; o; o >>= 1) s += __shfl_xor_sync(0xffffffffu, s, o);
    if (l == 0) out[2 * B_DIM * H_DIM + r] = -logf(s);
}

// =========================== persistent kernel ===========================
__global__ __launch_bounds__(TPB, 2)
void decode_persistent(const float* __restrict__ X,
                       const float* __restrict__ Kt,
                       const float* __restrict__ Vt,
                       const float* __restrict__ query,
                       const float* __restrict__ state1,
                       const float* __restrict__ state2,
                       const float* __restrict__ varfeat,
                       const void*  __restrict__ mask,
                       const float* __restrict__ nnQ,
                       const float* __restrict__ nnO,
                       const float* __restrict__ nnA,
                       const float* __restrict__ nnB,
                       const float* __restrict__ nnW,
                       const float* __restrict__ Wih,
                       const float* __restrict__ Whh,
                       const float* __restrict__ bih,
                       const float* __restrict__ bhh,
                       float* __restrict__ out) {
    stage_probe((const unsigned int*)mask);
    stage_lstm(query, state1, Wih, Whh, bih, bhh, state2, out);
    gsync();
    stage_gem(out, nnQ, g_Qg, true);
    gsync();
    stage_attn(Kt, Vt, mask);
    gsync();
    stage_gem(g_xg, nnO, g_qm, false);
    gsync();
    stage_logits(X, varfeat, mask, nnA, nnB, nnW);
    gsync();
    stage_choose(out);
}

// ---------------- launch ----------------
extern "C" void kernel_launch(void* const* d_in, const int* in_sizes, int n_in,
                              void* d_out, int out_size) {
    const float* X       = (const float*)d_in[0];
    const float* Kt      = (const float*)d_in[1];
    const float* Vt      = (const float*)d_in[2];
    const float* query   = (const float*)d_in[3];
    const float* state1  = (const float*)d_in[4];
    const float* state2  = (const float*)d_in[5];
    const float* varfeat = (const float*)d_in[6];
    const void*  mask    = (const void*) d_in[7];
    const float* nnQ     = (const float*)d_in[8];
    const float* nnO     = (const float*)d_in[9];
    const float* nnA     = (const float*)d_in[10];
    const float* nnB     = (const float*)d_in[11];
    const float* nnW     = (const float*)d_in[12];
    const float* Wih     = (const float*)d_in[13];
    const float* Whh     = (const float*)d_in[14];
    const float* bih     = (const float*)d_in[15];
    const float* bhh     = (const float*)d_in[16];
    float* out = (float*)d_out;

    decode_persistent<<<GRID, TPB>>>(X, Kt, Vt, query, state1, state2, varfeat,
                                     mask, nnQ, nnO, nnA, nnB, nnW,
                                     Wih, Whh, bih, bhh, out);
}

// round 8
// speedup vs baseline: 1.6421x; 1.2512x over previous
#include <cuda_runtime.h>
#include <cuda_bf16.h>
#include <math.h>

// Problem constants
#define NP 64
#define NR 8
#define NK 500
#define H_DIM 256
#define HEADS 8
#define HD 32
#define VD 8
#define B_DIM (NP*NR)          // 512
#define KCH 25

#define GRID 256
#define TPB 256

#define NEG_INF (__int_as_float(0xff800000))

// ---------------- scratch ----------------
__device__ float g_Qg[B_DIM * H_DIM];
__device__ float g_xg[B_DIM * H_DIM];
__device__ float g_qm[B_DIM * H_DIM];
__device__ float g_L[B_DIM * NK];
__device__ unsigned g_flags;
__device__ unsigned g_cnt = 0;
__device__ unsigned g_gen = 0;

// ---------------- global software barrier (replay-safe) ----------------
__device__ __forceinline__ void gsync() {
    __syncthreads();
    if (threadIdx.x == 0) {
        volatile unsigned* vgen = &g_gen;
        __threadfence();
        unsigned my = *vgen;
        unsigned v = atomicAdd(&g_cnt, 1u);
        if (v == (unsigned)(GRID - 1)) {
            g_cnt = 0u;
            __threadfence();
            atomicAdd(&g_gen, 1u);
        } else {
            while (*vgen == my) __nanosleep(32);
        }
        __threadfence();
    }
    __syncthreads();
}

// ---------------- helpers ----------------
__device__ __forceinline__ float tanh_fast(float x) {
    x = fminf(fmaxf(x, -15.f), 15.f);
    float e = __expf(2.f * x);
    return __fdividef(e - 1.f, e + 1.f);
}
__device__ __forceinline__ float tanh_approx(float x) {
    float y;
    asm("tanh.approx.f32 %0, %1;" : "=f"(y) : "f"(x));
    return y;
}
__device__ __forceinline__ float sigmoid_f(float x) {
    return 1.f / (1.f + __expf(-x));
}
__device__ __forceinline__ int load_maskmode() {
    unsigned f = *(volatile unsigned*)&g_flags;
    return (f & 2u) ? 2 : ((f & 1u) ? 1 : 0);
}
__device__ __forceinline__ bool get_mask(const void* m, int idx, int mode) {
    if (mode == 2) return ((const unsigned char*)m)[idx] != 0;
    if (mode == 1) return ((const float*)m)[idx] != 0.0f;
    return ((const int*)m)[idx] != 0;
}
__device__ __forceinline__ float dot4(float4 a, float4 b, float acc) {
    return fmaf(a.x, b.x, fmaf(a.y, b.y, fmaf(a.z, b.z, fmaf(a.w, b.w, acc))));
}

// ---------------- shared memory ----------------
union SmemU {
    struct { float As[32][36]; float Bs[64][36]; } lstm;                        // 13.8KB
    struct { float As[16][36]; float BsT[32][36]; } gem;                        // 6.9KB
    struct { float Qs[NR*HD]; float Ss[NK*NR]; float xp[8][NR][HD]; float sinv[NR]; } attn; // 25.2KB
    struct { float qs[NR*H_DIM]; float As[VD*H_DIM]; float B[H_DIM]; float vfs[VD][KCH]; } lg; // 17.8KB
};
__shared__ SmemU sm;

// =========================== stages ===========================

__device__ void stage_probe(const unsigned int* __restrict__ m) {
    unsigned local = 0;
    for (int i = blockIdx.x * TPB + threadIdx.x; i < 64000; i += GRID * TPB) {
        unsigned v = m[i];
        if (v == 0x3F800000u) local |= 1u;
        else if (v > 1u) local |= 2u;
    }
#pragma unroll
    for (int o = 16; o; o >>= 1) local |= __shfl_xor_sync(0xffffffffu, local, o);
    if ((threadIdx.x & 31) == 0 && local) atomicOr(&g_flags, local);
}

// LSTM GEMM + fused activation. 256 tiles: 32 m x 16 cols (x4 gates).
__device__ void stage_lstm(const float* __restrict__ query,
                           const float* __restrict__ state1,
                           const float* __restrict__ Wih,
                           const float* __restrict__ Whh,
                           const float* __restrict__ bih,
                           const float* __restrict__ bhh,
                           const float* __restrict__ state2,
                           float* __restrict__ out) {
    int tile = blockIdx.x;
    if (tile >= 256) return;
    int m0 = (tile >> 4) * 32;
    int colbase = (tile & 15) * 16;
    int tid = threadIdx.x;
    int r = tid >> 5, c = tid & 31;          // loader coords
    int ty = tid >> 4, tx = tid & 15;        // compute: m pair = ty, col = tx
    float acc[2][4] = {};
    int nrow[8];
#pragma unroll
    for (int i = 0; i < 8; ++i) {
        int j = r + i * 8;                   // 0..63: gate = j>>4, col = j&15
        nrow[i] = (j >> 4) * 256 + colbase + (j & 15);
    }
    float ra[4], rb[8];
#pragma unroll
    for (int i = 0; i < 4; ++i) ra[i] = query[(m0 + r + i * 8) * 256 + c];
#pragma unroll
    for (int i = 0; i < 8; ++i) rb[i] = Wih[nrow[i] * 256 + c];
    for (int kt = 0; kt < 16; ++kt) {
#pragma unroll
        for (int i = 0; i < 4; ++i) sm.lstm.As[r + i * 8][c] = ra[i];
#pragma unroll
        for (int i = 0; i < 8; ++i) sm.lstm.Bs[r + i * 8][c] = rb[i];
        __syncthreads();
        if (kt < 15) {
            int kg = (kt + 1) * 32;
            const float* Ap = (kg < 256) ? query : state1;
            const float* Bp = (kg < 256) ? Wih : Whh;
            int kof = kg & 255;
#pragma unroll
            for (int i = 0; i < 4; ++i) ra[i] = Ap[(m0 + r + i * 8) * 256 + kof + c];
#pragma unroll
            for (int i = 0; i < 8; ++i) rb[i] = Bp[nrow[i] * 256 + kof + c];
        }
#pragma unroll
        for (int kc = 0; kc < 8; ++kc) {
            float4 a0 = *(const float4*)&sm.lstm.As[ty * 2][kc * 4];
            float4 a1 = *(const float4*)&sm.lstm.As[ty * 2 + 1][kc * 4];
#pragma unroll
            for (int g = 0; g < 4; ++g) {
                float4 b = *(const float4*)&sm.lstm.Bs[g * 16 + tx][kc * 4];
                acc[0][g] = dot4(a0, b, acc[0][g]);
                acc[1][g] = dot4(a1, b, acc[1][g]);
            }
        }
        __syncthreads();
    }
    int col = colbase + tx;
#pragma unroll
    for (int i = 0; i < 2; ++i) {
        int m = m0 + ty * 2 + i;
        int idx = m * 256 + col;
        float gi = acc[i][0] + bih[col]       + bhh[col];
        float gf = acc[i][1] + bih[256 + col] + bhh[256 + col];
        float gg = acc[i][2] + bih[512 + col] + bhh[512 + col];
        float go = acc[i][3] + bih[768 + col] + bhh[768 + col];
        float cc = sigmoid_f(gf) * state2[idx] + sigmoid_f(gi) * tanh_fast(gg);
        float hh = sigmoid_f(go) * tanh_fast(cc);
        out[idx] = hh;
        out[B_DIM * H_DIM + idx] = cc;
    }
}

// Generic 512x256x256 GEMM, tile 16m x 32n, 256 tiles. B staged transposed.
__device__ void stage_gem(const float* __restrict__ A,
                          const float* __restrict__ Bm,
                          float* __restrict__ C, bool isQ) {
    int tile = blockIdx.x;
    if (tile >= 256) return;
    int m0 = (tile >> 3) * 16;
    int n0 = (tile & 7) * 32;
    int tid = threadIdx.x;
    int r = tid >> 5, c = tid & 31;
    int ty = tid >> 5, tx = tid & 31;
    float acc[2] = {};
    const float* Bbase = isQ ? (Bm + (n0 >> 5) * (H_DIM * HD)) : (Bm + n0);
    int bstride = isQ ? HD : H_DIM;
    float ra[2], rb[4];
#pragma unroll
    for (int i = 0; i < 2; ++i) ra[i] = A[(m0 + r + i * 8) * 256 + c];
#pragma unroll
    for (int i = 0; i < 4; ++i) rb[i] = Bbase[(r + i * 8) * bstride + c];
    for (int kt = 0; kt < 8; ++kt) {
#pragma unroll
        for (int i = 0; i < 2; ++i) sm.gem.As[r + i * 8][c] = ra[i];
#pragma unroll
        for (int i = 0; i < 4; ++i) sm.gem.BsT[c][r + i * 8] = rb[i];   // transpose
        __syncthreads();
        if (kt < 7) {
            int k0 = (kt + 1) * 32;
#pragma unroll
            for (int i = 0; i < 2; ++i) ra[i] = A[(m0 + r + i * 8) * 256 + k0 + c];
#pragma unroll
            for (int i = 0; i < 4; ++i) rb[i] = Bbase[(k0 + r + i * 8) * bstride + c];
        }
#pragma unroll
        for (int kc = 0; kc < 8; ++kc) {
            float4 a0 = *(const float4*)&sm.gem.As[ty * 2][kc * 4];
            float4 a1 = *(const float4*)&sm.gem.As[ty * 2 + 1][kc * 4];
            float4 b  = *(const float4*)&sm.gem.BsT[tx][kc * 4];
            acc[0] = dot4(a0, b, acc[0]);
            acc[1] = dot4(a1, b, acc[1]);
        }
        __syncthreads();
    }
    float scale = isQ ? 0.17677669529663687f : 1.0f;
    C[(m0 + ty * 2) * 256 + n0 + tx]     = acc[0] * scale;
    C[(m0 + ty * 2 + 1) * 256 + n0 + tx] = acc[1] * scale;
}

__device__ void stage_attn(const float* __restrict__ Kt,
                           const float* __restrict__ Vt,
                           const void* __restrict__ mask) {
    int tid = threadIdx.x;
    int w = tid >> 5, l = tid & 31;
    int mode = load_maskmode();
    for (int job = blockIdx.x; job < NP * HEADS; job += GRID) {
        int p = job & 63, a = job >> 6;
        __syncthreads();
        sm.attn.Qs[tid] = g_Qg[(p * NR + w) * H_DIM + a * HD + l];
        __syncthreads();

        // S pass: dual-k per thread (k and k+256), doubles outstanding loads
        const float* Kbase = Kt + ((size_t)(a * NP + p)) * NK * HD;
        {
            int ka = tid;                        // 0..255
            int kb = tid + 256;                  // 256..511
            bool hasb = kb < NK;
            const float4* kra = (const float4*)(Kbase + ka * HD);
            const float4* krb = (const float4*)(Kbase + (hasb ? kb : 0) * HD);
            float acca[NR] = {}, accb[NR] = {};
#pragma unroll
            for (int d4 = 0; d4 < 8; ++d4) {
                float4 kva = kra[d4];
                float4 kvb = krb[d4];
#pragma unroll
                for (int q = 0; q < NR; ++q) {
                    float4 qv = *(const float4*)(sm.attn.Qs + q * HD + d4 * 4);
                    acca[q] = dot4(qv, kva, acca[q]);
                    accb[q] = dot4(qv, kvb, accb[q]);
                }
            }
            *(float4*)&sm.attn.Ss[ka * 8]     = make_float4(acca[0], acca[1], acca[2], acca[3]);
            *(float4*)&sm.attn.Ss[ka * 8 + 4] = make_float4(acca[4], acca[5], acca[6], acca[7]);
            if (hasb) {
                *(float4*)&sm.attn.Ss[kb * 8]     = make_float4(accb[0], accb[1], accb[2], accb[3]);
                *(float4*)&sm.attn.Ss[kb * 8 + 4] = make_float4(accb[4], accb[5], accb[6], accb[7]);
            }
        }
        __syncthreads();

        // softmax per q (warp w = q)
        {
            int q = w;
            int mbase = p * (NR * NK) + q * NK;
            float mx = NEG_INF;
            for (int k = l; k < NK; k += 32) {
                float v = sm.attn.Ss[k * 8 + q];
                if (get_mask(mask, mbase + k, mode)) { v = NEG_INF; sm.attn.Ss[k * 8 + q] = v; }
                mx = fmaxf(mx, v);
            }
#pragma unroll
            for (int o = 16; o; o >>= 1) mx = fmaxf(mx, __shfl_xor_sync(0xffffffffu, mx, o));
            float s = 0.f;
            for (int k = l; k < NK; k += 32) {
                float e = __expf(sm.attn.Ss[k * 8 + q] - mx);
                sm.attn.Ss[k * 8 + q] = e;
                s += e;
            }
#pragma unroll
            for (int o = 16; o; o >>= 1) s += __shfl_xor_sync(0xffffffffu, s, o);
            if (l == 0) sm.attn.sinv[q] = 1.f / s;
        }
        __syncthreads();

        // x = P @ V : warp owns a k-chunk; V loads batched 8-deep for MLP
        {
            int k0 = (NK * w) / 8, k1 = (NK * (w + 1)) / 8;
            float acc[NR] = {};
            const float* Vb = Vt + ((size_t)(a * NP + p)) * NK * HD + l;
            int k = k0;
            for (; k + 8 <= k1; k += 8) {
                float v[8];
#pragma unroll
                for (int i = 0; i < 8; ++i) v[i] = Vb[(k + i) * HD];
#pragma unroll
                for (int i = 0; i < 8; ++i) {
                    float4 p0 = *(const float4*)&sm.attn.Ss[(k + i) * 8];
                    float4 p1 = *(const float4*)&sm.attn.Ss[(k + i) * 8 + 4];
                    acc[0] = fmaf(p0.x, v[i], acc[0]);
                    acc[1] = fmaf(p0.y, v[i], acc[1]);
                    acc[2] = fmaf(p0.z, v[i], acc[2]);
                    acc[3] = fmaf(p0.w, v[i], acc[3]);
                    acc[4] = fmaf(p1.x, v[i], acc[4]);
                    acc[5] = fmaf(p1.y, v[i], acc[5]);
                    acc[6] = fmaf(p1.z, v[i], acc[6]);
                    acc[7] = fmaf(p1.w, v[i], acc[7]);
                }
            }
            for (; k < k1; ++k) {
                float v = Vb[k * HD];
                float4 p0 = *(const float4*)&sm.attn.Ss[k * 8];
                float4 p1 = *(const float4*)&sm.attn.Ss[k * 8 + 4];
                acc[0] = fmaf(p0.x, v, acc[0]);
                acc[1] = fmaf(p0.y, v, acc[1]);
                acc[2] = fmaf(p0.z, v, acc[2]);
                acc[3] = fmaf(p0.w, v, acc[3]);
                acc[4] = fmaf(p1.x, v, acc[4]);
                acc[5] = fmaf(p1.y, v, acc[5]);
                acc[6] = fmaf(p1.z, v, acc[6]);
                acc[7] = fmaf(p1.w, v, acc[7]);
            }
#pragma unroll
            for (int q = 0; q < NR; ++q) sm.attn.xp[w][q][l] = acc[q];
        }
        __syncthreads();
        {
            float s = 0.f;
#pragma unroll
            for (int u = 0; u < 8; ++u) s += sm.attn.xp[u][w][l];
            g_xg[(p * NR + w) * H_DIM + a * HD + l] = s * sm.attn.sinv[w];
        }
    }
}

// logits: lane l owns h = l*8 .. l*8+7; X prefetched one k-iter ahead
__device__ void stage_logits(const float* __restrict__ X,
                             const float* __restrict__ varfeat,
                             const void* __restrict__ mask,
                             const float* __restrict__ nnA,
                             const float* __restrict__ nnB,
                             const float* __restrict__ nnW) {
    int tid = threadIdx.x, w = tid >> 5, l = tid & 31;
    int mode = load_maskmode();
    float4 Wv0 = *(const float4*)(nnW + l * 8);
    float4 Wv1 = *(const float4*)(nnW + l * 8 + 4);
    const int NJOB = NP * (NK / KCH);            // 1280
    for (int job = blockIdx.x; job < NJOB; job += GRID) {
        int p = job / 20;
        int kbase = (job % 20) * KCH;
        __syncthreads();
        for (int e = tid; e < NR * H_DIM; e += 256) {
            sm.lg.qs[e] = g_qm[p * NR * H_DIM + e];
            sm.lg.As[e] = nnA[e];
        }
        sm.lg.B[tid] = nnB[tid];
        if (tid < VD * KCH) {
            int v = tid / KCH, kk = tid % KCH;
            sm.lg.vfs[v][kk] = varfeat[(p * VD + v) * NK + kbase + kk];
        }
        __syncthreads();

        float4 B0 = *(const float4*)&sm.lg.B[l * 8];
        float4 B1 = *(const float4*)&sm.lg.B[l * 8 + 4];

        int kend = kbase + KCH;
        int k = kbase + w;
        const float* Xp = X + ((size_t)p * NK + k) * H_DIM + l * 8;
        float4 x0 = *(const float4*)Xp;
        float4 x1 = *(const float4*)(Xp + 4);
        for (; k < kend; k += 8) {
            float4 cx0 = x0, cx1 = x1;
            int kn = k + 8;
            if (kn < kend) {               // prefetch next iteration's X
                const float* Xn = X + ((size_t)p * NK + kn) * H_DIM + l * 8;
                x0 = *(const float4*)Xn;
                x1 = *(const float4*)(Xn + 4);
            }
            int kk = k - kbase;
            int mb = p * (NR * NK) + k;
            bool mk[NR];
#pragma unroll
            for (int q = 0; q < NR; ++q) mk[q] = get_mask(mask, mb + q * NK, mode);

            float base[8];
            base[0] = cx0.x + B0.x; base[1] = cx0.y + B0.y;
            base[2] = cx0.z + B0.z; base[3] = cx0.w + B0.w;
            base[4] = cx1.x + B1.x; base[5] = cx1.y + B1.y;
            base[6] = cx1.z + B1.z; base[7] = cx1.w + B1.w;
#pragma unroll
            for (int v = 0; v < VD; ++v) {
                float f = sm.lg.vfs[v][kk];
                float4 a0 = *(const float4*)&sm.lg.As[v * H_DIM + l * 8];
                float4 a1 = *(const float4*)&sm.lg.As[v * H_DIM + l * 8 + 4];
                base[0] = fmaf(f, a0.x, base[0]); base[1] = fmaf(f, a0.y, base[1]);
                base[2] = fmaf(f, a0.z, base[2]); base[3] = fmaf(f, a0.w, base[3]);
                base[4] = fmaf(f, a1.x, base[4]); base[5] = fmaf(f, a1.y, base[5]);
                base[6] = fmaf(f, a1.z, base[6]); base[7] = fmaf(f, a1.w, base[7]);
            }
#pragma unroll
            for (int q = 0; q < NR; ++q) {
                float outv;
                if (mk[q]) {
                    outv = NEG_INF;
                } else {
                    float4 q0 = *(const float4*)&sm.lg.qs[q * H_DIM + l * 8];
                    float4 q1 = *(const float4*)&sm.lg.qs[q * H_DIM + l * 8 + 4];
                    float s;
                    s = tanh_approx(base[0] + q0.x) * Wv0.x;
                    s = fmaf(tanh_approx(base[1] + q0.y), Wv0.y, s);
                    s = fmaf(tanh_approx(base[2] + q0.z), Wv0.z, s);
                    s = fmaf(tanh_approx(base[3] + q0.w), Wv0.w, s);
                    s = fmaf(tanh_approx(base[4] + q1.x), Wv1.x, s);
                    s = fmaf(tanh_approx(base[5] + q1.y), Wv1.y, s);
                    s = fmaf(tanh_approx(base[6] + q1.z), Wv1.z, s);
                    s = fmaf(tanh_approx(base[7] + q1.w), Wv1.w, s);
#pragma unroll
                    for (int o = 16; o; o >>= 1) s += __shfl_xor_sync(0xffffffffu, s, o);
                    outv = 10.f * tanh_fast(s);
                }
                if (l == 0) g_L[(p * NR + q) * NK + k] = outv;
            }
        }
    }
}

__device__ void stage_choose(float* __restrict__ out) {
    int w = threadIdx.x >> 5, l = threadIdx.x & 31;
    int r = blockIdx.x * 8 + w;
    if (r >= B_DIM) return;
    const float* Lr = g_L + r * NK;
    float best = NEG_INF;
    for (int k = l; k < NK; k += 32) best = fmaxf(best, Lr[k]);
#pragma unroll
    for (int o = 16; o; o >>= 1) best = fmaxf(best, __shfl_xor_sync(0xffffffffu, best, o));
    float s = 0.f;
    for (int k = l; k < NK; k += 32) {
        float v = Lr[k];
        if (v > NEG_INF) s += __expf(v - best);
    }
#pragma unroll
    for (int o = 16; o; o >>= 1) s += __shfl_xor_sync(0xffffffffu, s, o);
    if (l == 0) out[2 * B_DIM * H_DIM + r] = -logf(s);
}

// =========================== persistent kernel ===========================
__global__ __launch_bounds__(TPB, 2)
void decode_persistent(const float* __restrict__ X,
                       const float* __restrict__ Kt,
                       const float* __restrict__ Vt,
                       const float* __restrict__ query,
                       const float* __restrict__ state1,
                       const float* __restrict__ state2,
                       const float* __restrict__ varfeat,
                       const void*  __restrict__ mask,
                       const float* __restrict__ nnQ,
                       const float* __restrict__ nnO,
                       const float* __restrict__ nnA,
                       const float* __restrict__ nnB,
                       const float* __restrict__ nnW,
                       const float* __restrict__ Wih,
                       const float* __restrict__ Whh,
                       const float* __restrict__ bih,
                       const float* __restrict__ bhh,
                       float* __restrict__ out) {
    stage_probe((const unsigned int*)mask);
    stage_lstm(query, state1, Wih, Whh, bih, bhh, state2, out);
    gsync();
    stage_gem(out, nnQ, g_Qg, true);
    gsync();
    stage_attn(Kt, Vt, mask);
    gsync();
    stage_gem(g_xg, nnO, g_qm, false);
    gsync();
    stage_logits(X, varfeat, mask, nnA, nnB, nnW);
    gsync();
    stage_choose(out);
}

// ---------------- launch ----------------
extern "C" void kernel_launch(void* const* d_in, const int* in_sizes, int n_in,
                              void* d_out, int out_size) {
    const float* X       = (const float*)d_in[0];
    const float* Kt      = (const float*)d_in[1];
    const float* Vt      = (const float*)d_in[2];
    const float* query   = (const float*)d_in[3];
    const float* state1  = (const float*)d_in[4];
    const float* state2  = (const float*)d_in[5];
    const float* varfeat = (const float*)d_in[6];
    const void*  mask    = (const void*) d_in[7];
    const float* nnQ     = (const float*)d_in[8];
    const float* nnO     = (const float*)d_in[9];
    const float* nnA     = (const float*)d_in[10];
    const float* nnB     = (const float*)d_in[11];
    const float* nnW     = (const float*)d_in[12];
    const float* Wih     = (const float*)d_in[13];
    const float* Whh     = (const float*)d_in[14];
    const float* bih     = (const float*)d_in[15];
    const float* bhh     = (const float*)d_in[16];
    float* out = (float*)d_out;

    decode_persistent<<<GRID, TPB>>>(X, Kt, Vt, query, state1, state2, varfeat,
                                     mask, nnQ, nnO, nnA, nnB, nnW,
                                     Wih, Whh, bih, bhh, out);
}

// round 9
// speedup vs baseline: 1.6607x; 1.0113x over previous
#include <cuda_runtime.h>
#include <cuda_bf16.h>
#include <math.h>

// Problem constants
#define NP 64
#define NR 8
#define NK 500
#define H_DIM 256
#define HEADS 8
#define HD 32
#define VD 8
#define B_DIM (NP*NR)          // 512
#define KCH 25

#define GRID 256
#define TPB 256

#define NEG_INF (__int_as_float(0xff800000))

// ---------------- scratch ----------------
__device__ float g_Qg[B_DIM * H_DIM];
__device__ float g_xg[B_DIM * H_DIM];
__device__ float g_qm[B_DIM * H_DIM];
__device__ float g_L[B_DIM * NK];
__device__ unsigned g_flags;
__device__ unsigned g_cnt = 0;
__device__ unsigned g_gen = 0;

// ---------------- global software barrier (replay-safe) ----------------
__device__ __forceinline__ void gsync() {
    __syncthreads();
    if (threadIdx.x == 0) {
        volatile unsigned* vgen = &g_gen;
        __threadfence();
        unsigned my = *vgen;
        unsigned v = atomicAdd(&g_cnt, 1u);
        if (v == (unsigned)(GRID - 1)) {
            g_cnt = 0u;
            __threadfence();
            atomicAdd(&g_gen, 1u);
        } else {
            while (*vgen == my) __nanosleep(32);
        }
        __threadfence();
    }
    __syncthreads();
}

// ---------------- helpers ----------------
__device__ __forceinline__ float tanh_fast(float x) {
    x = fminf(fmaxf(x, -15.f), 15.f);
    float e = __expf(2.f * x);
    return __fdividef(e - 1.f, e + 1.f);
}
__device__ __forceinline__ float tanh_approx(float x) {
    float y;
    asm("tanh.approx.f32 %0, %1;" : "=f"(y) : "f"(x));
    return y;
}
__device__ __forceinline__ float sigmoid_f(float x) {
    return 1.f / (1.f + __expf(-x));
}
__device__ __forceinline__ int load_maskmode() {
    unsigned f = *(volatile unsigned*)&g_flags;
    return (f & 2u) ? 2 : ((f & 1u) ? 1 : 0);
}
__device__ __forceinline__ bool get_mask(const void* m, int idx, int mode) {
    if (mode == 2) return ((const unsigned char*)m)[idx] != 0;
    if (mode == 1) return ((const float*)m)[idx] != 0.0f;
    return ((const int*)m)[idx] != 0;
}
__device__ __forceinline__ float dot4(float4 a, float4 b, float acc) {
    return fmaf(a.x, b.x, fmaf(a.y, b.y, fmaf(a.z, b.z, fmaf(a.w, b.w, acc))));
}

// ---------------- shared memory ----------------
struct AttnSm {
    float Qs[NR * HD];                      // 1KB
    float Ss[NR * 512];                     // 16KB, [q][512]
    union {
        float Kc[2][64][36];                // 18KB K staging (S-pass)
        float xp[8][NR][HD];                // 8KB  (V-pass epilogue)
    } u;
    float sinv[NR];
};
union SmemU {
    struct { float As[32][36]; float Bs[64][36]; } lstm;                        // 13.8KB
    struct { float As[16][36]; float BsT[32][36]; } gem;                        // 6.9KB
    AttnSm attn;                                                                // 35KB
    struct { float qs[NR*H_DIM]; float As[VD*H_DIM]; float B[H_DIM]; float vfs[VD][KCH]; } lg; // 17.8KB
};
__shared__ SmemU sm;

// =========================== stages ===========================

__device__ void stage_probe(const unsigned int* __restrict__ m) {
    unsigned local = 0;
    for (int i = blockIdx.x * TPB + threadIdx.x; i < 64000; i += GRID * TPB) {
        unsigned v = m[i];
        if (v == 0x3F800000u) local |= 1u;
        else if (v > 1u) local |= 2u;
    }
#pragma unroll
    for (int o = 16; o; o >>= 1) local |= __shfl_xor_sync(0xffffffffu, local, o);
    if ((threadIdx.x & 31) == 0 && local) atomicOr(&g_flags, local);
}

// LSTM GEMM + fused activation. 256 tiles: 32 m x 16 cols (x4 gates).
__device__ void stage_lstm(const float* __restrict__ query,
                           const float* __restrict__ state1,
                           const float* __restrict__ Wih,
                           const float* __restrict__ Whh,
                           const float* __restrict__ bih,
                           const float* __restrict__ bhh,
                           const float* __restrict__ state2,
                           float* __restrict__ out) {
    int tile = blockIdx.x;
    if (tile >= 256) return;
    int m0 = (tile >> 4) * 32;
    int colbase = (tile & 15) * 16;
    int tid = threadIdx.x;
    int r = tid >> 5, c = tid & 31;
    int ty = tid >> 4, tx = tid & 15;
    float acc[2][4] = {};
    int nrow[8];
#pragma unroll
    for (int i = 0; i < 8; ++i) {
        int j = r + i * 8;
        nrow[i] = (j >> 4) * 256 + colbase + (j & 15);
    }
    float ra[4], rb[8];
#pragma unroll
    for (int i = 0; i < 4; ++i) ra[i] = query[(m0 + r + i * 8) * 256 + c];
#pragma unroll
    for (int i = 0; i < 8; ++i) rb[i] = Wih[nrow[i] * 256 + c];
    for (int kt = 0; kt < 16; ++kt) {
#pragma unroll
        for (int i = 0; i < 4; ++i) sm.lstm.As[r + i * 8][c] = ra[i];
#pragma unroll
        for (int i = 0; i < 8; ++i) sm.lstm.Bs[r + i * 8][c] = rb[i];
        __syncthreads();
        if (kt < 15) {
            int kg = (kt + 1) * 32;
            const float* Ap = (kg < 256) ? query : state1;
            const float* Bp = (kg < 256) ? Wih : Whh;
            int kof = kg & 255;
#pragma unroll
            for (int i = 0; i < 4; ++i) ra[i] = Ap[(m0 + r + i * 8) * 256 + kof + c];
#pragma unroll
            for (int i = 0; i < 8; ++i) rb[i] = Bp[nrow[i] * 256 + kof + c];
        }
#pragma unroll
        for (int kc = 0; kc < 8; ++kc) {
            float4 a0 = *(const float4*)&sm.lstm.As[ty * 2][kc * 4];
            float4 a1 = *(const float4*)&sm.lstm.As[ty * 2 + 1][kc * 4];
#pragma unroll
            for (int g = 0; g < 4; ++g) {
                float4 b = *(const float4*)&sm.lstm.Bs[g * 16 + tx][kc * 4];
                acc[0][g] = dot4(a0, b, acc[0][g]);
                acc[1][g] = dot4(a1, b, acc[1][g]);
            }
        }
        __syncthreads();
    }
    int col = colbase + tx;
#pragma unroll
    for (int i = 0; i < 2; ++i) {
        int m = m0 + ty * 2 + i;
        int idx = m * 256 + col;
        float gi = acc[i][0] + bih[col]       + bhh[col];
        float gf = acc[i][1] + bih[256 + col] + bhh[256 + col];
        float gg = acc[i][2] + bih[512 + col] + bhh[512 + col];
        float go = acc[i][3] + bih[768 + col] + bhh[768 + col];
        float cc = sigmoid_f(gf) * state2[idx] + sigmoid_f(gi) * tanh_fast(gg);
        float hh = sigmoid_f(go) * tanh_fast(cc);
        out[idx] = hh;
        out[B_DIM * H_DIM + idx] = cc;
    }
}

// Generic 512x256x256 GEMM, tile 16m x 32n, 256 tiles. B staged transposed.
__device__ void stage_gem(const float* __restrict__ A,
                          const float* __restrict__ Bm,
                          float* __restrict__ C, bool isQ) {
    int tile = blockIdx.x;
    if (tile >= 256) return;
    int m0 = (tile >> 3) * 16;
    int n0 = (tile & 7) * 32;
    int tid = threadIdx.x;
    int r = tid >> 5, c = tid & 31;
    int ty = tid >> 5, tx = tid & 31;
    float acc[2] = {};
    const float* Bbase = isQ ? (Bm + (n0 >> 5) * (H_DIM * HD)) : (Bm + n0);
    int bstride = isQ ? HD : H_DIM;
    float ra[2], rb[4];
#pragma unroll
    for (int i = 0; i < 2; ++i) ra[i] = A[(m0 + r + i * 8) * 256 + c];
#pragma unroll
    for (int i = 0; i < 4; ++i) rb[i] = Bbase[(r + i * 8) * bstride + c];
    for (int kt = 0; kt < 8; ++kt) {
#pragma unroll
        for (int i = 0; i < 2; ++i) sm.gem.As[r + i * 8][c] = ra[i];
#pragma unroll
        for (int i = 0; i < 4; ++i) sm.gem.BsT[c][r + i * 8] = rb[i];
        __syncthreads();
        if (kt < 7) {
            int k0 = (kt + 1) * 32;
#pragma unroll
            for (int i = 0; i < 2; ++i) ra[i] = A[(m0 + r + i * 8) * 256 + k0 + c];
#pragma unroll
            for (int i = 0; i < 4; ++i) rb[i] = Bbase[(k0 + r + i * 8) * bstride + c];
        }
#pragma unroll
        for (int kc = 0; kc < 8; ++kc) {
            float4 a0 = *(const float4*)&sm.gem.As[ty * 2][kc * 4];
            float4 a1 = *(const float4*)&sm.gem.As[ty * 2 + 1][kc * 4];
            float4 b  = *(const float4*)&sm.gem.BsT[tx][kc * 4];
            acc[0] = dot4(a0, b, acc[0]);
            acc[1] = dot4(a1, b, acc[1]);
        }
        __syncthreads();
    }
    float scale = isQ ? 0.17677669529663687f : 1.0f;
    C[(m0 + ty * 2) * 256 + n0 + tx]     = acc[0] * scale;
    C[(m0 + ty * 2 + 1) * 256 + n0 + tx] = acc[1] * scale;
}

__device__ void stage_attn(const float* __restrict__ Kt,
                           const float* __restrict__ Vt,
                           const void* __restrict__ mask) {
    int tid = threadIdx.x;
    int w = tid >> 5, l = tid & 31;
    int mode = load_maskmode();
    int rl = tid & 63;                 // row within 64-row chunk
    int qp = (tid >> 6) * 2;           // q-pair base
    for (int job = blockIdx.x; job < NP * HEADS; job += GRID) {
        int p = job & 63, a = job >> 6;
        __syncthreads();
        sm.attn.Qs[tid] = g_Qg[(p * NR + w) * H_DIM + a * HD + l];
        __syncthreads();

        const float* Kbase = Kt + ((size_t)(a * NP + p)) * NK * HD;
        const float4* K4 = (const float4*)Kbase;     // 4000 float4s per job

        // ---- S pass: smem-staged K, coalesced loads, double-buffered ----
        float4 ld0, ld1;
        {
            int i0 = tid, i1 = tid + 256;
            ld0 = K4[i0];                            // i0 < 512 always valid
            ld1 = K4[i1 < 4000 ? i1 : 0];
        }
        for (int ch = 0; ch < 8; ++ch) {
            int buf = ch & 1;
            {   // store staged chunk (conflict-free-ish scalarized via float4)
                int i0 = tid, i1 = tid + 256;
                float* d0 = &sm.attn.u.Kc[buf][i0 >> 3][(i0 & 7) * 4];
                d0[0] = ld0.x; d0[1] = ld0.y; d0[2] = ld0.z; d0[3] = ld0.w;
                float* d1 = &sm.attn.u.Kc[buf][i1 >> 3][(i1 & 7) * 4];
                d1[0] = ld1.x; d1[1] = ld1.y; d1[2] = ld1.z; d1[3] = ld1.w;
            }
            __syncthreads();
            if (ch < 7) {
                int b = (ch + 1) * 512;
                int i0 = b + tid, i1 = b + tid + 256;
                ld0 = K4[i0 < 4000 ? i0 : 0];
                ld1 = K4[i1 < 4000 ? i1 : 0];
            }
            int kg = ch * 64 + rl;
            if (kg < NK) {
                float a0 = 0.f, a1 = 0.f;
#pragma unroll
                for (int d4 = 0; d4 < 8; ++d4) {
                    float4 kv = *(const float4*)&sm.attn.u.Kc[buf][rl][d4 * 4];
                    float4 q0 = *(const float4*)&sm.attn.Qs[qp * HD + d4 * 4];
                    float4 q1 = *(const float4*)&sm.attn.Qs[(qp + 1) * HD + d4 * 4];
                    a0 = dot4(q0, kv, a0);
                    a1 = dot4(q1, kv, a1);
                }
                sm.attn.Ss[qp * 512 + kg]       = a0;
                sm.attn.Ss[(qp + 1) * 512 + kg] = a1;
            }
        }
        __syncthreads();

        // ---- softmax per q (warp w = q), conflict-free [q][512] ----
        {
            int q = w;
            int mbase = p * (NR * NK) + q * NK;
            float* Sq = &sm.attn.Ss[q * 512];
            float mx = NEG_INF;
            for (int k = l; k < NK; k += 32) {
                float v = Sq[k];
                if (get_mask(mask, mbase + k, mode)) { v = NEG_INF; Sq[k] = v; }
                mx = fmaxf(mx, v);
            }
#pragma unroll
            for (int o = 16; o; o >>= 1) mx = fmaxf(mx, __shfl_xor_sync(0xffffffffu, mx, o));
            float s = 0.f;
            for (int k = l; k < NK; k += 32) {
                float e = __expf(Sq[k] - mx);
                Sq[k] = e;
                s += e;
            }
#pragma unroll
            for (int o = 16; o; o >>= 1) s += __shfl_xor_sync(0xffffffffu, s, o);
            if (l == 0) sm.attn.sinv[q] = 1.f / s;
        }
        __syncthreads();

        // ---- x = P @ V : warp owns k-chunk; 4-k vectorized P reads ----
        {
            int k0 = (NK * w) / 8, k1 = (NK * (w + 1)) / 8;
            float acc[NR] = {};
            const float* Vb = Vt + ((size_t)(a * NP + p)) * NK * HD + l;
            int k = k0;
            for (; (k & 3) && k < k1; ++k) {         // align to 4
                float v = Vb[k * HD];
#pragma unroll
                for (int q = 0; q < NR; ++q)
                    acc[q] = fmaf(sm.attn.Ss[q * 512 + k], v, acc[q]);
            }
            for (; k + 4 <= k1; k += 4) {
                float4 vv;
                vv.x = Vb[k * HD]; vv.y = Vb[(k + 1) * HD];
                vv.z = Vb[(k + 2) * HD]; vv.w = Vb[(k + 3) * HD];
#pragma unroll
                for (int q = 0; q < NR; ++q) {
                    float4 P = *(const float4*)&sm.attn.Ss[q * 512 + k];
                    acc[q] = dot4(P, vv, acc[q]);
                }
            }
            for (; k < k1; ++k) {
                float v = Vb[k * HD];
#pragma unroll
                for (int q = 0; q < NR; ++q)
                    acc[q] = fmaf(sm.attn.Ss[q * 512 + k], v, acc[q]);
            }
            __syncthreads();   // Kc buffers (overlaying xp) fully done
#pragma unroll
            for (int q = 0; q < NR; ++q) sm.attn.u.xp[w][q][l] = acc[q];
        }
        __syncthreads();
        {
            float s = 0.f;
#pragma unroll
            for (int u = 0; u < 8; ++u) s += sm.attn.u.xp[u][w][l];
            g_xg[(p * NR + w) * H_DIM + a * HD + l] = s * sm.attn.sinv[w];
        }
    }
}

// logits: lane l owns h = l*8 .. l*8+7; X prefetched; 9-shuffle reduction
__device__ void stage_logits(const float* __restrict__ X,
                             const float* __restrict__ varfeat,
                             const void* __restrict__ mask,
                             const float* __restrict__ nnA,
                             const float* __restrict__ nnB,
                             const float* __restrict__ nnW) {
    int tid = threadIdx.x, w = tid >> 5, l = tid & 31;
    int mode = load_maskmode();
    float4 Wv0 = *(const float4*)(nnW + l * 8);
    float4 Wv1 = *(const float4*)(nnW + l * 8 + 4);
    const int NJOB = NP * (NK / KCH);            // 1280
    for (int job = blockIdx.x; job < NJOB; job += GRID) {
        int p = job / 20;
        int kbase = (job % 20) * KCH;
        __syncthreads();
        for (int e = tid; e < NR * H_DIM; e += 256) {
            sm.lg.qs[e] = g_qm[p * NR * H_DIM + e];
            sm.lg.As[e] = nnA[e];
        }
        sm.lg.B[tid] = nnB[tid];
        if (tid < VD * KCH) {
            int v = tid / KCH, kk = tid % KCH;
            sm.lg.vfs[v][kk] = varfeat[(p * VD + v) * NK + kbase + kk];
        }
        __syncthreads();

        float4 B0 = *(const float4*)&sm.lg.B[l * 8];
        float4 B1 = *(const float4*)&sm.lg.B[l * 8 + 4];

        int kend = kbase + KCH;
        int k = kbase + w;
        const float* Xp = X + ((size_t)p * NK + k) * H_DIM + l * 8;
        float4 x0 = *(const float4*)Xp;
        float4 x1 = *(const float4*)(Xp + 4);
        for (; k < kend; k += 8) {
            float4 cx0 = x0, cx1 = x1;
            int kn = k + 8;
            if (kn < kend) {
                const float* Xn = X + ((size_t)p * NK + kn) * H_DIM + l * 8;
                x0 = *(const float4*)Xn;
                x1 = *(const float4*)(Xn + 4);
            }
            int kk = k - kbase;
            int mb = p * (NR * NK) + k;
            bool mk[NR];
#pragma unroll
            for (int q = 0; q < NR; ++q) mk[q] = get_mask(mask, mb + q * NK, mode);

            float base[8];
            base[0] = cx0.x + B0.x; base[1] = cx0.y + B0.y;
            base[2] = cx0.z + B0.z; base[3] = cx0.w + B0.w;
            base[4] = cx1.x + B1.x; base[5] = cx1.y + B1.y;
            base[6] = cx1.z + B1.z; base[7] = cx1.w + B1.w;
#pragma unroll
            for (int v = 0; v < VD; ++v) {
                float f = sm.lg.vfs[v][kk];
                float4 a0 = *(const float4*)&sm.lg.As[v * H_DIM + l * 8];
                float4 a1 = *(const float4*)&sm.lg.As[v * H_DIM + l * 8 + 4];
                base[0] = fmaf(f, a0.x, base[0]); base[1] = fmaf(f, a0.y, base[1]);
                base[2] = fmaf(f, a0.z, base[2]); base[3] = fmaf(f, a0.w, base[3]);
                base[4] = fmaf(f, a1.x, base[4]); base[5] = fmaf(f, a1.y, base[5]);
                base[6] = fmaf(f, a1.z, base[6]); base[7] = fmaf(f, a1.w, base[7]);
            }
            float s[8];
#pragma unroll
            for (int q = 0; q < NR; ++q) {
                if (mk[q]) { s[q] = 0.f; continue; }
                float4 q0 = *(const float4*)&sm.lg.qs[q * H_DIM + l * 8];
                float4 q1 = *(const float4*)&sm.lg.qs[q * H_DIM + l * 8 + 4];
                float t;
                t = tanh_approx(base[0] + q0.x) * Wv0.x;
                t = fmaf(tanh_approx(base[1] + q0.y), Wv0.y, t);
                t = fmaf(tanh_approx(base[2] + q0.z), Wv0.z, t);
                t = fmaf(tanh_approx(base[3] + q0.w), Wv0.w, t);
                t = fmaf(tanh_approx(base[4] + q1.x), Wv1.x, t);
                t = fmaf(tanh_approx(base[5] + q1.y), Wv1.y, t);
                t = fmaf(tanh_approx(base[6] + q1.z), Wv1.z, t);
                t = fmaf(tanh_approx(base[7] + q1.w), Wv1.w, t);
                s[q] = t;
            }
            // 9-shuffle multi-value butterfly: lane group l>>2 ends with sum for q=l>>2
            {
                bool lo;
                lo = (l & 16) == 0;
#pragma unroll
                for (int j = 0; j < 4; ++j) {
                    float v = lo ? s[j + 4] : s[j];
                    float t = __shfl_xor_sync(0xffffffffu, v, 16);
                    s[j] = (lo ? s[j] : s[j + 4]) + t;
                }
                lo = (l & 8) == 0;
#pragma unroll
                for (int j = 0; j < 2; ++j) {
                    float v = lo ? s[j + 2] : s[j];
                    float t = __shfl_xor_sync(0xffffffffu, v, 8);
                    s[j] = (lo ? s[j] : s[j + 2]) + t;
                }
                lo = (l & 4) == 0;
                {
                    float v = lo ? s[1] : s[0];
                    float t = __shfl_xor_sync(0xffffffffu, v, 4);
                    s[0] = (lo ? s[0] : s[1]) + t;
                }
                s[0] += __shfl_xor_sync(0xffffffffu, s[0], 2);
                s[0] += __shfl_xor_sync(0xffffffffu, s[0], 1);
            }
            if ((l & 3) == 0) {
                int q = l >> 2;
                float outv = mk[q] ? NEG_INF : 10.f * tanh_fast(s[0]);
                g_L[(p * NR + q) * NK + k] = outv;
            }
        }
    }
}

__device__ void stage_choose(float* __restrict__ out) {
    int w = threadIdx.x >> 5, l = threadIdx.x & 31;
    int r = blockIdx.x * 8 + w;
    if (r >= B_DIM) return;
    const float* Lr = g_L + r * NK;
    float best = NEG_INF;
    for (int k = l; k < NK; k += 32) best = fmaxf(best, Lr[k]);
#pragma unroll
    for (int o = 16; o; o >>= 1) best = fmaxf(best, __shfl_xor_sync(0xffffffffu, best, o));
    float s = 0.f;
    for (int k = l; k < NK; k += 32) {
        float v = Lr[k];
        if (v > NEG_INF) s += __expf(v - best);
    }
#pragma unroll
    for (int o = 16; o; o >>= 1) s += __shfl_xor_sync(0xffffffffu, s, o);
    if (l == 0) out[2 * B_DIM * H_DIM + r] = -logf(s);
}

// =========================== persistent kernel ===========================
__global__ __launch_bounds__(TPB, 2)
void decode_persistent(const float* __restrict__ X,
                       const float* __restrict__ Kt,
                       const float* __restrict__ Vt,
                       const float* __restrict__ query,
                       const float* __restrict__ state1,
                       const float* __restrict__ state2,
                       const float* __restrict__ varfeat,
                       const void*  __restrict__ mask,
                       const float* __restrict__ nnQ,
                       const float* __restrict__ nnO,
                       const float* __restrict__ nnA,
                       const float* __restrict__ nnB,
                       const float* __restrict__ nnW,
                       const float* __restrict__ Wih,
                       const float* __restrict__ Whh,
                       const float* __restrict__ bih,
                       const float* __restrict__ bhh,
                       float* __restrict__ out) {
    stage_probe((const unsigned int*)mask);
    stage_lstm(query, state1, Wih, Whh, bih, bhh, state2, out);
    gsync();
    stage_gem(out, nnQ, g_Qg, true);
    gsync();
    stage_attn(Kt, Vt, mask);
    gsync();
    stage_gem(g_xg, nnO, g_qm, false);
    gsync();
    stage_logits(X, varfeat, mask, nnA, nnB, nnW);
    gsync();
    stage_choose(out);
}

// ---------------- launch ----------------
extern "C" void kernel_launch(void* const* d_in, const int* in_sizes, int n_in,
                              void* d_out, int out_size) {
    const float* X       = (const float*)d_in[0];
    const float* Kt      = (const float*)d_in[1];
    const float* Vt      = (const float*)d_in[2];
    const float* query   = (const float*)d_in[3];
    const float* state1  = (const float*)d_in[4];
    const float* state2  = (const float*)d_in[5];
    const float* varfeat = (const float*)d_in[6];
    const void*  mask    = (const void*) d_in[7];
    const float* nnQ     = (const float*)d_in[8];
    const float* nnO     = (const float*)d_in[9];
    const float* nnA     = (const float*)d_in[10];
    const float* nnB     = (const float*)d_in[11];
    const float* nnW     = (const float*)d_in[12];
    const float* Wih     = (const float*)d_in[13];
    const float* Whh     = (const float*)d_in[14];
    const float* bih     = (const float*)d_in[15];
    const float* bhh     = (const float*)d_in[16];
    float* out = (float*)d_out;

    decode_persistent<<<GRID, TPB>>>(X, Kt, Vt, query, state1, state2, varfeat,
                                     mask, nnQ, nnO, nnA, nnB, nnW,
                                     Wih, Whh, bih, bhh, out);
}

// round 14
// speedup vs baseline: 1.8175x; 1.0944x over previous
#include <cuda_runtime.h>
#include <cuda_bf16.h>
#include <math.h>

// Problem constants
#define NP 64
#define NR 8
#define NK 500
#define H_DIM 256
#define HEADS 8
#define HD 32
#define VD 8
#define B_DIM (NP*NR)          // 512
#define KCH 25

#define GRID 256
#define TPB 256

#define NEG_INF (__int_as_float(0xff800000))

// ---------------- scratch ----------------
__device__ float g_Qg[B_DIM * H_DIM];
__device__ float g_xg[B_DIM * H_DIM];
__device__ float g_qm[B_DIM * H_DIM];
__device__ float g_L[B_DIM * NK];
__device__ unsigned g_flags;
__device__ unsigned g_cnt = 0;
__device__ unsigned g_gen = 0;

// ---------------- shared memory ----------------
struct AttnSm {
    float Qs[NR * HD];                      // 1KB
    float Ss[NR * 512];                     // 16KB, [q][512]
    union {
        float Kc[4][64][36];                // 36KB K staging (cp.async, 4 bufs)
        float xp[8][NR][HD];                // 8KB  (V-pass epilogue)
    } u;
    float sinv[NR];
};
union SmemU {
    struct { float As[32][36]; float Bs[64][36]; } lstm;
    struct { float As[16][36]; float BsT[32][36]; } gem;
    AttnSm attn;                                                                // ~54KB
    struct { float qs[NR*H_DIM]; float As[VD*H_DIM]; float B[H_DIM]; float vfs[VD][KCH]; } lg;
};

__device__ __forceinline__ SmemU& smem_ref() {
    extern __shared__ unsigned char dynsm[];
    return *reinterpret_cast<SmemU*>(dynsm);
}

// ---------------- global software barrier (replay-safe) ----------------
__device__ __forceinline__ void gsync() {
    __syncthreads();
    if (threadIdx.x == 0) {
        volatile unsigned* vgen = &g_gen;
        __threadfence();
        unsigned my = *vgen;
        unsigned v = atomicAdd(&g_cnt, 1u);
        if (v == (unsigned)(GRID - 1)) {
            g_cnt = 0u;
            __threadfence();
            atomicAdd(&g_gen, 1u);
        } else {
            while (*vgen == my) __nanosleep(32);
        }
        __threadfence();
    }
    __syncthreads();
}

// ---------------- helpers ----------------
__device__ __forceinline__ float tanh_fast(float x) {
    x = fminf(fmaxf(x, -15.f), 15.f);
    float e = __expf(2.f * x);
    return __fdividef(e - 1.f, e + 1.f);
}
__device__ __forceinline__ float tanh_approx(float x) {
    float y;
    asm("tanh.approx.f32 %0, %1;" : "=f"(y) : "f"(x));
    return y;
}
__device__ __forceinline__ float sigmoid_f(float x) {
    return 1.f / (1.f + __expf(-x));
}
__device__ __forceinline__ int load_maskmode() {
    unsigned f = *(volatile unsigned*)&g_flags;
    return (f & 2u) ? 2 : ((f & 1u) ? 1 : 0);
}
__device__ __forceinline__ bool get_mask(const void* m, int idx, int mode) {
    if (mode == 2) return ((const unsigned char*)m)[idx] != 0;
    if (mode == 1) return ((const float*)m)[idx] != 0.0f;
    return ((const int*)m)[idx] != 0;
}
__device__ __forceinline__ float dot4(float4 a, float4 b, float acc) {
    return fmaf(a.x, b.x, fmaf(a.y, b.y, fmaf(a.z, b.z, fmaf(a.w, b.w, acc))));
}
__device__ __forceinline__ unsigned saddr(const void* p) {
    return (unsigned)__cvta_generic_to_shared(p);
}
__device__ __forceinline__ void cp_async16(unsigned s, const void* g) {
    asm volatile("cp.async.cg.shared.global [%0], [%1], 16;" :: "r"(s), "l"(g));
}
__device__ __forceinline__ void cp_commit() { asm volatile("cp.async.commit_group;"); }
__device__ __forceinline__ void cp_wait2() { asm volatile("cp.async.wait_group 2;"); }
__device__ __forceinline__ void cp_wait0() { asm volatile("cp.async.wait_group 0;"); }

// =========================== stages ===========================

__device__ void stage_probe(const unsigned int* __restrict__ m) {
    unsigned local = 0;
    for (int i = blockIdx.x * TPB + threadIdx.x; i < 64000; i += GRID * TPB) {
        unsigned v = m[i];
        if (v == 0x3F800000u) local |= 1u;
        else if (v > 1u) local |= 2u;
    }
#pragma unroll
    for (int o = 16; o; o >>= 1) local |= __shfl_xor_sync(0xffffffffu, local, o);
    if ((threadIdx.x & 31) == 0 && local) atomicOr(&g_flags, local);
}

// LSTM GEMM + fused activation. 256 tiles: 32 m x 16 cols (x4 gates).
__device__ void stage_lstm(const float* __restrict__ query,
                           const float* __restrict__ state1,
                           const float* __restrict__ Wih,
                           const float* __restrict__ Whh,
                           const float* __restrict__ bih,
                           const float* __restrict__ bhh,
                           const float* __restrict__ state2,
                           float* __restrict__ out) {
    SmemU& sm = smem_ref();
    int tile = blockIdx.x;
    if (tile >= 256) return;
    int m0 = (tile >> 4) * 32;
    int colbase = (tile & 15) * 16;
    int tid = threadIdx.x;
    int r = tid >> 5, c = tid & 31;
    int ty = tid >> 4, tx = tid & 15;
    float acc[2][4] = {};
    int nrow[8];
#pragma unroll
    for (int i = 0; i < 8; ++i) {
        int j = r + i * 8;
        nrow[i] = (j >> 4) * 256 + colbase + (j & 15);
    }
    float ra[4], rb[8];
#pragma unroll
    for (int i = 0; i < 4; ++i) ra[i] = query[(m0 + r + i * 8) * 256 + c];
#pragma unroll
    for (int i = 0; i < 8; ++i) rb[i] = Wih[nrow[i] * 256 + c];
    for (int kt = 0; kt < 16; ++kt) {
#pragma unroll
        for (int i = 0; i < 4; ++i) sm.lstm.As[r + i * 8][c] = ra[i];
#pragma unroll
        for (int i = 0; i < 8; ++i) sm.lstm.Bs[r + i * 8][c] = rb[i];
        __syncthreads();
        if (kt < 15) {
            int kg = (kt + 1) * 32;
            const float* Ap = (kg < 256) ? query : state1;
            const float* Bp = (kg < 256) ? Wih : Whh;
            int kof = kg & 255;
#pragma unroll
            for (int i = 0; i < 4; ++i) ra[i] = Ap[(m0 + r + i * 8) * 256 + kof + c];
#pragma unroll
            for (int i = 0; i < 8; ++i) rb[i] = Bp[nrow[i] * 256 + kof + c];
        }
#pragma unroll
        for (int kc = 0; kc < 8; ++kc) {
            float4 a0 = *(const float4*)&sm.lstm.As[ty * 2][kc * 4];
            float4 a1 = *(const float4*)&sm.lstm.As[ty * 2 + 1][kc * 4];
#pragma unroll
            for (int g = 0; g < 4; ++g) {
                float4 b = *(const float4*)&sm.lstm.Bs[g * 16 + tx][kc * 4];
                acc[0][g] = dot4(a0, b, acc[0][g]);
                acc[1][g] = dot4(a1, b, acc[1][g]);
            }
        }
        __syncthreads();
    }
    int col = colbase + tx;
#pragma unroll
    for (int i = 0; i < 2; ++i) {
        int m = m0 + ty * 2 + i;
        int idx = m * 256 + col;
        float gi = acc[i][0] + bih[col]       + bhh[col];
        float gf = acc[i][1] + bih[256 + col] + bhh[256 + col];
        float gg = acc[i][2] + bih[512 + col] + bhh[512 + col];
        float go = acc[i][3] + bih[768 + col] + bhh[768 + col];
        float cc = sigmoid_f(gf) * state2[idx] + sigmoid_f(gi) * tanh_fast(gg);
        float hh = sigmoid_f(go) * tanh_fast(cc);
        out[idx] = hh;
        out[B_DIM * H_DIM + idx] = cc;
    }
}

// Generic 512x256x256 GEMM, tile 16m x 32n, 256 tiles. B staged transposed.
__device__ void stage_gem(const float* __restrict__ A,
                          const float* __restrict__ Bm,
                          float* __restrict__ C, bool isQ) {
    SmemU& sm = smem_ref();
    int tile = blockIdx.x;
    if (tile >= 256) return;
    int m0 = (tile >> 3) * 16;
    int n0 = (tile & 7) * 32;
    int tid = threadIdx.x;
    int r = tid >> 5, c = tid & 31;
    int ty = tid >> 5, tx = tid & 31;
    float acc[2] = {};
    const float* Bbase = isQ ? (Bm + (n0 >> 5) * (H_DIM * HD)) : (Bm + n0);
    int bstride = isQ ? HD : H_DIM;
    float ra[2], rb[4];
#pragma unroll
    for (int i = 0; i < 2; ++i) ra[i] = A[(m0 + r + i * 8) * 256 + c];
#pragma unroll
    for (int i = 0; i < 4; ++i) rb[i] = Bbase[(r + i * 8) * bstride + c];
    for (int kt = 0; kt < 8; ++kt) {
#pragma unroll
        for (int i = 0; i < 2; ++i) sm.gem.As[r + i * 8][c] = ra[i];
#pragma unroll
        for (int i = 0; i < 4; ++i) sm.gem.BsT[c][r + i * 8] = rb[i];
        __syncthreads();
        if (kt < 7) {
            int k0 = (kt + 1) * 32;
#pragma unroll
            for (int i = 0; i < 2; ++i) ra[i] = A[(m0 + r + i * 8) * 256 + k0 + c];
#pragma unroll
            for (int i = 0; i < 4; ++i) rb[i] = Bbase[(k0 + r + i * 8) * bstride + c];
        }
#pragma unroll
        for (int kc = 0; kc < 8; ++kc) {
            float4 a0 = *(const float4*)&sm.gem.As[ty * 2][kc * 4];
            float4 a1 = *(const float4*)&sm.gem.As[ty * 2 + 1][kc * 4];
            float4 b  = *(const float4*)&sm.gem.BsT[tx][kc * 4];
            acc[0] = dot4(a0, b, acc[0]);
            acc[1] = dot4(a1, b, acc[1]);
        }
        __syncthreads();
    }
    float scale = isQ ? 0.17677669529663687f : 1.0f;
    C[(m0 + ty * 2) * 256 + n0 + tx]     = acc[0] * scale;
    C[(m0 + ty * 2 + 1) * 256 + n0 + tx] = acc[1] * scale;
}

__device__ void stage_attn(const float* __restrict__ Kt,
                           const float* __restrict__ Vt,
                           const void* __restrict__ mask) {
    SmemU& sm = smem_ref();
    int tid = threadIdx.x;
    int w = tid >> 5, l = tid & 31;
    int mode = load_maskmode();
    int rl = tid & 63;                 // row within 64-row chunk
    int qp = (tid >> 6) * 2;           // q-pair base
    for (int job = blockIdx.x; job < NP * HEADS; job += GRID) {
        int p = job & 63, a = job >> 6;
        __syncthreads();
        sm.attn.Qs[tid] = g_Qg[(p * NR + w) * H_DIM + a * HD + l];

        const float* Kbase = Kt + ((size_t)(a * NP + p)) * NK * HD;
        const float4* K4 = (const float4*)Kbase;     // 4000 float4s per job

        // ---- S pass: cp.async 4-buffer pipeline, depth 3 ----
        int t1 = tid + 256;
        unsigned d0base = saddr(&sm.attn.u.Kc[0][tid >> 3][(tid & 7) * 4]);
        unsigned d1base = saddr(&sm.attn.u.Kc[0][t1 >> 3][(t1 & 7) * 4]);
        const unsigned bufBytes = sizeof(sm.attn.u.Kc[0]);
        // prologue: chunks 0,1,2
#pragma unroll
        for (int ch = 0; ch < 3; ++ch) {
            int b = ch * 512;
            int i0 = b + tid, i1 = b + t1;
            if (i0 < 4000) cp_async16(d0base + ch * bufBytes, K4 + i0);
            if (i1 < 4000) cp_async16(d1base + ch * bufBytes, K4 + i1);
            cp_commit();
        }
        __syncthreads();     // Qs visible (piggyback)
        for (int ch = 0; ch < 8; ++ch) {
            cp_wait2();
            __syncthreads();
            int cn = ch + 3;
            if (cn < 8) {
                int b = cn * 512;
                int i0 = b + tid, i1 = b + t1;
                int buf = cn & 3;
                if (i0 < 4000) cp_async16(d0base + buf * bufBytes, K4 + i0);
                if (i1 < 4000) cp_async16(d1base + buf * bufBytes, K4 + i1);
            }
            cp_commit();     // empty groups at tail keep wait(2) uniform
            int buf = ch & 3;
            int kg = ch * 64 + rl;
            if (kg < NK) {
                float a0 = 0.f, a1 = 0.f;
#pragma unroll
                for (int d4 = 0; d4 < 8; ++d4) {
                    float4 kv = *(const float4*)&sm.attn.u.Kc[buf][rl][d4 * 4];
                    float4 q0 = *(const float4*)&sm.attn.Qs[qp * HD + d4 * 4];
                    float4 q1 = *(const float4*)&sm.attn.Qs[(qp + 1) * HD + d4 * 4];
                    a0 = dot4(q0, kv, a0);
                    a1 = dot4(q1, kv, a1);
                }
                sm.attn.Ss[qp * 512 + kg]       = a0;
                sm.attn.Ss[(qp + 1) * 512 + kg] = a1;
            }
        }
        cp_wait0();
        __syncthreads();

        // ---- softmax per q (warp w = q), conflict-free [q][512] ----
        {
            int q = w;
            int mbase = p * (NR * NK) + q * NK;
            float* Sq = &sm.attn.Ss[q * 512];
            float mx = NEG_INF;
            for (int k = l; k < NK; k += 32) {
                float v = Sq[k];
                if (get_mask(mask, mbase + k, mode)) { v = NEG_INF; Sq[k] = v; }
                mx = fmaxf(mx, v);
            }
#pragma unroll
            for (int o = 16; o; o >>= 1) mx = fmaxf(mx, __shfl_xor_sync(0xffffffffu, mx, o));
            float s = 0.f;
            for (int k = l; k < NK; k += 32) {
                float e = __expf(Sq[k] - mx);
                Sq[k] = e;
                s += e;
            }
#pragma unroll
            for (int o = 16; o; o >>= 1) s += __shfl_xor_sync(0xffffffffu, s, o);
            if (l == 0) sm.attn.sinv[q] = 1.f / s;
        }
        __syncthreads();

        // ---- x = P @ V : warp owns rows [64w, min(64w+64, NK)); 8-deep batches ----
        {
            int k0 = w * 64;
            int k1 = min(k0 + 64, NK);
            float acc[NR] = {};
            const float* Vb = Vt + ((size_t)(a * NP + p)) * NK * HD + l;
            float vc[8], vn[8];
            int k = k0;
            if (k + 8 <= k1) {
#pragma unroll
                for (int i = 0; i < 8; ++i) vc[i] = Vb[(k + i) * HD];
            }
            for (; k + 8 <= k1; k += 8) {
                if (k + 16 <= k1) {
#pragma unroll
                    for (int i = 0; i < 8; ++i) vn[i] = Vb[(k + 8 + i) * HD];
                }
#pragma unroll
                for (int q = 0; q < NR; ++q) {
                    float4 P0 = *(const float4*)&sm.attn.Ss[q * 512 + k];
                    float4 P1 = *(const float4*)&sm.attn.Ss[q * 512 + k + 4];
                    float4 v0 = make_float4(vc[0], vc[1], vc[2], vc[3]);
                    float4 v1 = make_float4(vc[4], vc[5], vc[6], vc[7]);
                    acc[q] = dot4(P0, v0, acc[q]);
                    acc[q] = dot4(P1, v1, acc[q]);
                }
#pragma unroll
                for (int i = 0; i < 8; ++i) vc[i] = vn[i];
            }
            for (; k < k1; ++k) {
                float v = Vb[k * HD];
#pragma unroll
                for (int q = 0; q < NR; ++q)
                    acc[q] = fmaf(sm.attn.Ss[q * 512 + k], v, acc[q]);
            }
            __syncthreads();   // Kc (overlaying xp) fully consumed
#pragma unroll
            for (int q = 0; q < NR; ++q) sm.attn.u.xp[w][q][l] = acc[q];
        }
        __syncthreads();
        {
            float s = 0.f;
#pragma unroll
            for (int u = 0; u < 8; ++u) s += sm.attn.u.xp[u][w][l];
            g_xg[(p * NR + w) * H_DIM + a * HD + l] = s * sm.attn.sinv[w];
        }
    }
}

// logits: lane l owns h = l*8 .. l*8+7; X prefetched; 9-shuffle reduction
__device__ void stage_logits(const float* __restrict__ X,
                             const float* __restrict__ varfeat,
                             const void* __restrict__ mask,
                             const float* __restrict__ nnA,
                             const float* __restrict__ nnB,
                             const float* __restrict__ nnW) {
    SmemU& sm = smem_ref();
    int tid = threadIdx.x, w = tid >> 5, l = tid & 31;
    int mode = load_maskmode();
    float4 Wv0 = *(const float4*)(nnW + l * 8);
    float4 Wv1 = *(const float4*)(nnW + l * 8 + 4);
    const int NJOB = NP * (NK / KCH);            // 1280
    for (int job = blockIdx.x; job < NJOB; job += GRID) {
        int p = job / 20;
        int kbase = (job % 20) * KCH;
        __syncthreads();
        for (int e = tid; e < NR * H_DIM; e += 256) {
            sm.lg.qs[e] = g_qm[p * NR * H_DIM + e];
            sm.lg.As[e] = nnA[e];
        }
        sm.lg.B[tid] = nnB[tid];
        if (tid < VD * KCH) {
            int v = tid / KCH, kk = tid % KCH;
            sm.lg.vfs[v][kk] = varfeat[(p * VD + v) * NK + kbase + kk];
        }
        __syncthreads();

        float4 B0 = *(const float4*)&sm.lg.B[l * 8];
        float4 B1 = *(const float4*)&sm.lg.B[l * 8 + 4];

        int kend = kbase + KCH;
        int k = kbase + w;
        const float* Xp = X + ((size_t)p * NK + k) * H_DIM + l * 8;
        float4 x0 = *(const float4*)Xp;
        float4 x1 = *(const float4*)(Xp + 4);
        for (; k < kend; k += 8) {
            float4 cx0 = x0, cx1 = x1;
            int kn = k + 8;
            if (kn < kend) {
                const float* Xn = X + ((size_t)p * NK + kn) * H_DIM + l * 8;
                x0 = *(const float4*)Xn;
                x1 = *(const float4*)(Xn + 4);
            }
            int kk = k - kbase;
            int mb = p * (NR * NK) + k;
            bool mk[NR];
#pragma unroll
            for (int q = 0; q < NR; ++q) mk[q] = get_mask(mask, mb + q * NK, mode);

            float base[8];
            base[0] = cx0.x + B0.x; base[1] = cx0.y + B0.y;
            base[2] = cx0.z + B0.z; base[3] = cx0.w + B0.w;
            base[4] = cx1.x + B1.x; base[5] = cx1.y + B1.y;
            base[6] = cx1.z + B1.z; base[7] = cx1.w + B1.w;
#pragma unroll
            for (int v = 0; v < VD; ++v) {
                float f = sm.lg.vfs[v][kk];
                float4 a0 = *(const float4*)&sm.lg.As[v * H_DIM + l * 8];
                float4 a1 = *(const float4*)&sm.lg.As[v * H_DIM + l * 8 + 4];
                base[0] = fmaf(f, a0.x, base[0]); base[1] = fmaf(f, a0.y, base[1]);
                base[2] = fmaf(f, a0.z, base[2]); base[3] = fmaf(f, a0.w, base[3]);
                base[4] = fmaf(f, a1.x, base[4]); base[5] = fmaf(f, a1.y, base[5]);
                base[6] = fmaf(f, a1.z, base[6]); base[7] = fmaf(f, a1.w, base[7]);
            }
            float s[8];
#pragma unroll
            for (int q = 0; q < NR; ++q) {
                if (mk[q]) { s[q] = 0.f; continue; }
                float4 q0 = *(const float4*)&sm.lg.qs[q * H_DIM + l * 8];
                float4 q1 = *(const float4*)&sm.lg.qs[q * H_DIM + l * 8 + 4];
                float t;
                t = tanh_approx(base[0] + q0.x) * Wv0.x;
                t = fmaf(tanh_approx(base[1] + q0.y), Wv0.y, t);
                t = fmaf(tanh_approx(base[2] + q0.z), Wv0.z, t);
                t = fmaf(tanh_approx(base[3] + q0.w), Wv0.w, t);
                t = fmaf(tanh_approx(base[4] + q1.x), Wv1.x, t);
                t = fmaf(tanh_approx(base[5] + q1.y), Wv1.y, t);
                t = fmaf(tanh_approx(base[6] + q1.z), Wv1.z, t);
                t = fmaf(tanh_approx(base[7] + q1.w), Wv1.w, t);
                s[q] = t;
            }
            // 9-shuffle multi-value butterfly: lane 4q ends with sum for q
            {
                bool lo;
                lo = (l & 16) == 0;
#pragma unroll
                for (int j = 0; j < 4; ++j) {
                    float v = lo ? s[j + 4] : s[j];
                    float t = __shfl_xor_sync(0xffffffffu, v, 16);
                    s[j] = (lo ? s[j] : s[j + 4]) + t;
                }
                lo = (l & 8) == 0;
#pragma unroll
                for (int j = 0; j < 2; ++j) {
                    float v = lo ? s[j + 2] : s[j];
                    float t = __shfl_xor_sync(0xffffffffu, v, 8);
                    s[j] = (lo ? s[j] : s[j + 2]) + t;
                }
                lo = (l & 4) == 0;
                {
                    float v = lo ? s[1] : s[0];
                    float t = __shfl_xor_sync(0xffffffffu, v, 4);
                    s[0] = (lo ? s[0] : s[1]) + t;
                }
                s[0] += __shfl_xor_sync(0xffffffffu, s[0], 2);
                s[0] += __shfl_xor_sync(0xffffffffu, s[0], 1);
            }
            if ((l & 3) == 0) {
                int q = l >> 2;
                float outv = mk[q] ? NEG_INF : 10.f * tanh_fast(s[0]);
                g_L[(p * NR + q) * NK + k] = outv;
            }
        }
    }
}

__device__ void stage_choose(float* __restrict__ out) {
    int w = threadIdx.x >> 5, l = threadIdx.x & 31;
    int r = blockIdx.x * 8 + w;
    if (r >= B_DIM) return;
    const float* Lr = g_L + r * NK;
    float best = NEG_INF;
    for (int k = l; k < NK; k += 32) best = fmaxf(best, Lr[k]);
#pragma unroll
    for (int o = 16; o; o >>= 1) best = fmaxf(best, __shfl_xor_sync(0xffffffffu, best, o));
    float s = 0.f;
    for (int k = l; k < NK; k += 32) {
        float v = Lr[k];
        if (v > NEG_INF) s += __expf(v - best);
    }
#pragma unroll
    for (int o = 16; o; o >>= 1) s += __shfl_xor_sync(0xffffffffu, s, o);
    if (l == 0) out[2 * B_DIM * H_DIM + r] = -logf(s);
}

// =========================== persistent kernel ===========================
__global__ __launch_bounds__(TPB, 2)
void decode_persistent(const float* __restrict__ X,
                       const float* __restrict__ Kt,
                       const float* __restrict__ Vt,
                       const float* __restrict__ query,
                       const float* __restrict__ state1,
                       const float* __restrict__ state2,
                       const float* __restrict__ varfeat,
                       const void*  __restrict__ mask,
                       const float* __restrict__ nnQ,
                       const float* __restrict__ nnO,
                       const float* __restrict__ nnA,
                       const float* __restrict__ nnB,
                       const float* __restrict__ nnW,
                       const float* __restrict__ Wih,
                       const float* __restrict__ Whh,
                       const float* __restrict__ bih,
                       const float* __restrict__ bhh,
                       float* __restrict__ out) {
    stage_probe((const unsigned int*)mask);
    stage_lstm(query, state1, Wih, Whh, bih, bhh, state2, out);
    gsync();
    stage_gem(out, nnQ, g_Qg, true);
    gsync();
    stage_attn(Kt, Vt, mask);
    gsync();
    stage_gem(g_xg, nnO, g_qm, false);
    gsync();
    stage_logits(X, varfeat, mask, nnA, nnB, nnW);
    gsync();
    stage_choose(out);
}

// ---------------- launch ----------------
extern "C" void kernel_launch(void* const* d_in, const int* in_sizes, int n_in,
                              void* d_out, int out_size) {
    const float* X       = (const float*)d_in[0];
    const float* Kt      = (const float*)d_in[1];
    const float* Vt      = (const float*)d_in[2];
    const float* query   = (const float*)d_in[3];
    const float* state1  = (const float*)d_in[4];
    const float* state2  = (const float*)d_in[5];
    const float* varfeat = (const float*)d_in[6];
    const void*  mask    = (const void*) d_in[7];
    const float* nnQ     = (const float*)d_in[8];
    const float* nnO     = (const float*)d_in[9];
    const float* nnA     = (const float*)d_in[10];
    const float* nnB     = (const float*)d_in[11];
    const float* nnW     = (const float*)d_in[12];
    const float* Wih     = (const float*)d_in[13];
    const float* Whh     = (const float*)d_in[14];
    const float* bih     = (const float*)d_in[15];
    const float* bhh     = (const float*)d_in[16];
    float* out = (float*)d_out;

    cudaFuncSetAttribute(decode_persistent,
                         cudaFuncAttributeMaxDynamicSharedMemorySize,
                         (int)sizeof(SmemU));
    decode_persistent<<<GRID, TPB, sizeof(SmemU)>>>(
        X, Kt, Vt, query, state1, state2, varfeat,
        mask, nnQ, nnO, nnA, nnB, nnW,
        Wih, Whh, bih, bhh, out);
}